// round 1
// baseline (speedup 1.0000x reference)
#include <cuda_runtime.h>
#include <math.h>

#define HEADS 8
#define HD    64
#define BB    2
#define LL    2048
#define DD    512
#define OC    1536   // 3*HEADS*HD

// Scratch (device globals — no allocations allowed)
__device__ float g_qkv [BB * OC * LL];   // conv+swish output, [b, c, l]
__device__ float g_newv[BB * LL * DD];   // attention output, [b, l, h*HD+d]
__device__ float g_fc  [BB * LL * DD];   // fc+swish output,  [b, l, d]

__device__ __forceinline__ float swishf(float v) {
    return v / (1.f + __expf(-v));
}

// ---------------------------------------------------------------------------
// Kernel 1: Conv1d(D->OC, k=3, pad=1) + bias + swish, writes g_qkv[b][o][l]
// GEMM view: y[o,l] = sum_{i,k} w[o,i,k] * x[b, l+k-1, i]
// Tile: 128 o x 128 l, K-chunks of 16 i, 256 threads, 8x8 micro (strided)
// ---------------------------------------------------------------------------
__global__ void conv_kernel(const float* __restrict__ x,
                            const float* __restrict__ w,
                            const float* __restrict__ bias)
{
    __shared__ float sW[3][16][132];   // [k][i][o]
    __shared__ float sX[16][132];      // [i][j], j=0 <-> l0-1 (130 used)

    const int b  = blockIdx.z;
    const int o0 = blockIdx.y * 128;
    const int l0 = blockIdx.x * 128;
    const int tid = threadIdx.x;
    const int ty = tid >> 4;   // o-dir lane group (0..15)
    const int tx = tid & 15;   // l-dir lane group (0..15)

    float acc[8][8];
    #pragma unroll
    for (int s = 0; s < 8; s++)
        #pragma unroll
        for (int t = 0; t < 8; t++) acc[s][t] = 0.f;

    for (int i0 = 0; i0 < DD; i0 += 16) {
        // Load weights: 128 o x 16 i x 3 k = 6144 (coalesced runs of 48 floats)
        for (int idx = tid; idx < 6144; idx += 256) {
            int o_rel = idx / 48;
            int rem   = idx % 48;
            int i_rel = rem / 3;
            int k     = rem % 3;
            sW[k][i_rel][o_rel] = w[(size_t)(o0 + o_rel) * 1536 + (i0 + i_rel) * 3 + k];
        }
        // Load x slab: 16 i x 130 l (with halo), zero-pad at sequence edges
        for (int idx = tid; idx < 2080; idx += 256) {
            int j  = idx >> 4;       // 0..129
            int ii = idx & 15;
            int l  = l0 - 1 + j;
            float v = 0.f;
            if (l >= 0 && l < LL) v = x[((size_t)(b * LL + l)) * DD + i0 + ii];
            sX[ii][j] = v;
        }
        __syncthreads();

        #pragma unroll 2
        for (int ii = 0; ii < 16; ii++) {
            float wf[3][8];
            float xf[8][3];
            #pragma unroll
            for (int k = 0; k < 3; k++)
                #pragma unroll
                for (int s = 0; s < 8; s++) wf[k][s] = sW[k][ii][ty + 16 * s];
            #pragma unroll
            for (int t = 0; t < 8; t++)
                #pragma unroll
                for (int k = 0; k < 3; k++) xf[t][k] = sX[ii][tx + 16 * t + k];
            #pragma unroll
            for (int s = 0; s < 8; s++)
                #pragma unroll
                for (int t = 0; t < 8; t++)
                    #pragma unroll
                    for (int k = 0; k < 3; k++)
                        acc[s][t] += wf[k][s] * xf[t][k];
        }
        __syncthreads();
    }

    #pragma unroll
    for (int s = 0; s < 8; s++) {
        int o = o0 + ty + 16 * s;
        float bs = bias[o];
        #pragma unroll
        for (int t = 0; t < 8; t++) {
            int l = l0 + tx + 16 * t;
            g_qkv[((size_t)b * OC + o) * LL + l] = swishf(acc[s][t] + bs);
        }
    }
}

// ---------------------------------------------------------------------------
// Kernel 2: flash-style attention per (b, h, 64-row tile).
// q,k,v live in g_qkv channels [h*192 + {0,64,128} + d].
// scores = (q/sqrt(L))^T k ; online softmax ; O = P V^T -> g_newv[b,l,h*64+d]
// ---------------------------------------------------------------------------
__global__ void attn_kernel()
{
    extern __shared__ float sm[];
    float* sQ = sm;                 // [64][64]  (d, w)
    float* sK = sQ + 64 * 64;       // [64][64]  (d, m)
    float* sV = sK + 64 * 64;       // [64][65]  (d, m)  padded
    float* sP = sV + 64 * 65;       // [64][64]  (w, m)
    float* sM = sP + 64 * 64;       // [64]
    float* sL = sM + 64;            // [64]
    float* sS = sL + 64;            // [64] rescale factors

    const int b  = blockIdx.z;
    const int h  = blockIdx.y;
    const int w0 = blockIdx.x * 64;
    const int tid = threadIdx.x;
    const int ty = tid >> 4;
    const int tx = tid & 15;

    const float scale = rsqrtf((float)LL);
    const float* qbase = g_qkv + ((size_t)b * OC + h * 192) * LL;

    for (int idx = tid; idx < 4096; idx += 256) {
        int d = idx >> 6, ww = idx & 63;
        sQ[d * 64 + ww] = qbase[(size_t)d * LL + w0 + ww] * scale;
    }
    if (tid < 64) { sM[tid] = -1e30f; sL[tid] = 0.f; }

    float o_acc[4][4];
    #pragma unroll
    for (int i = 0; i < 4; i++)
        #pragma unroll
        for (int j = 0; j < 4; j++) o_acc[i][j] = 0.f;

    __syncthreads();

    for (int m0 = 0; m0 < LL; m0 += 64) {
        // Load K,V tiles
        for (int idx = tid; idx < 4096; idx += 256) {
            int d = idx >> 6, mm = idx & 63;
            sK[d * 64 + mm] = qbase[(size_t)(64 + d) * LL + m0 + mm];
            sV[d * 65 + mm] = qbase[(size_t)(128 + d) * LL + m0 + mm];
        }
        __syncthreads();

        // GEMM1: S[w][m] = sum_d Q[d][w] K[d][m]
        float sfr[4][4];
        #pragma unroll
        for (int i = 0; i < 4; i++)
            #pragma unroll
            for (int j = 0; j < 4; j++) sfr[i][j] = 0.f;
        for (int d = 0; d < 64; d++) {
            float qf[4], kf[4];
            #pragma unroll
            for (int i = 0; i < 4; i++) qf[i] = sQ[d * 64 + ty + 16 * i];
            #pragma unroll
            for (int j = 0; j < 4; j++) kf[j] = sK[d * 64 + tx + 16 * j];
            #pragma unroll
            for (int i = 0; i < 4; i++)
                #pragma unroll
                for (int j = 0; j < 4; j++) sfr[i][j] += qf[i] * kf[j];
        }
        #pragma unroll
        for (int i = 0; i < 4; i++)
            #pragma unroll
            for (int j = 0; j < 4; j++)
                sP[(ty + 16 * i) * 64 + tx + 16 * j] = sfr[i][j];
        __syncthreads();

        // Online softmax row pass (one thread per row)
        if (tid < 64) {
            int r = tid;
            float om = sM[r];
            float mx = om;
            for (int j = 0; j < 64; j++) mx = fmaxf(mx, sP[r * 64 + j]);
            float sc  = __expf(om - mx);
            float sum = 0.f;
            for (int j = 0; j < 64; j++) {
                float p = __expf(sP[r * 64 + j] - mx);
                sP[r * 64 + j] = p;
                sum += p;
            }
            sM[r] = mx;
            sL[r] = sL[r] * sc + sum;
            sS[r] = sc;
        }
        __syncthreads();

        // Rescale accumulators, then GEMM2: O[w][d] += sum_m P[w][m] V[d][m]
        #pragma unroll
        for (int i = 0; i < 4; i++) {
            float sc = sS[ty + 16 * i];
            #pragma unroll
            for (int j = 0; j < 4; j++) o_acc[i][j] *= sc;
        }
        for (int mm = 0; mm < 64; mm++) {
            float pf[4], vf[4];
            #pragma unroll
            for (int i = 0; i < 4; i++) pf[i] = sP[(ty + 16 * i) * 64 + mm];
            #pragma unroll
            for (int j = 0; j < 4; j++) vf[j] = sV[(tx + 16 * j) * 65 + mm];
            #pragma unroll
            for (int i = 0; i < 4; i++)
                #pragma unroll
                for (int j = 0; j < 4; j++) o_acc[i][j] += pf[i] * vf[j];
        }
        __syncthreads();
    }

    #pragma unroll
    for (int i = 0; i < 4; i++) {
        int ww = ty + 16 * i;
        float inv = 1.f / sL[ww];
        #pragma unroll
        for (int j = 0; j < 4; j++) {
            int d = tx + 16 * j;
            g_newv[((size_t)(b * LL) + w0 + ww) * DD + h * HD + d] = o_acc[i][j] * inv;
        }
    }
}

// ---------------------------------------------------------------------------
// Kernel 3: m = swish(new_v @ fc_w^T + fc_b) -> g_fc.  GEMM M=4096,N=512,K=512
// ---------------------------------------------------------------------------
__global__ void fc_kernel(const float* __restrict__ fw,
                          const float* __restrict__ fb)
{
    __shared__ float sA[32][65];   // [k][m]
    __shared__ float sB[32][65];   // [k][n]

    const int m0 = blockIdx.x * 64;
    const int n0 = blockIdx.y * 64;
    const int tid = threadIdx.x;
    const int ty = tid >> 4;
    const int tx = tid & 15;

    float acc[4][4];
    #pragma unroll
    for (int i = 0; i < 4; i++)
        #pragma unroll
        for (int j = 0; j < 4; j++) acc[i][j] = 0.f;

    for (int j0 = 0; j0 < DD; j0 += 32) {
        for (int idx = tid; idx < 2048; idx += 256) {
            int r  = idx >> 5;     // 0..63
            int kk = idx & 31;
            sA[kk][r] = g_newv[(size_t)(m0 + r) * DD + j0 + kk];
            sB[kk][r] = fw[(size_t)(n0 + r) * DD + j0 + kk];
        }
        __syncthreads();
        #pragma unroll 4
        for (int kk = 0; kk < 32; kk++) {
            float a[4], wv[4];
            #pragma unroll
            for (int i = 0; i < 4; i++) a[i]  = sA[kk][ty + 16 * i];
            #pragma unroll
            for (int j = 0; j < 4; j++) wv[j] = sB[kk][tx + 16 * j];
            #pragma unroll
            for (int i = 0; i < 4; i++)
                #pragma unroll
                for (int j = 0; j < 4; j++) acc[i][j] += a[i] * wv[j];
        }
        __syncthreads();
    }

    #pragma unroll
    for (int i = 0; i < 4; i++) {
        int mrow = m0 + ty + 16 * i;
        #pragma unroll
        for (int j = 0; j < 4; j++) {
            int n = n0 + tx + 16 * j;
            float c = acc[i][j] + fb[n];
            g_fc[(size_t)mrow * DD + n] = swishf(c);
        }
    }
}

// ---------------------------------------------------------------------------
// Kernel 4: out = layer_norm(2*x + g_fc). One warp per row of 512.
// ---------------------------------------------------------------------------
__global__ void ln_kernel(const float* __restrict__ x,
                          float* __restrict__ out)
{
    const int row  = blockIdx.x * 8 + (threadIdx.x >> 5);
    const int lane = threadIdx.x & 31;
    const float* mrow = g_fc + (size_t)row * DD;
    const float* xrow = x    + (size_t)row * DD;

    float tv[16];
    float sum = 0.f, sq = 0.f;
    #pragma unroll
    for (int t = 0; t < 16; t++) {
        int d = lane + 32 * t;
        float v = 2.f * xrow[d] + mrow[d];
        tv[t] = v;
        sum += v;
        sq  += v * v;
    }
    #pragma unroll
    for (int off = 16; off >= 1; off >>= 1) {
        sum += __shfl_xor_sync(0xffffffff, sum, off);
        sq  += __shfl_xor_sync(0xffffffff, sq,  off);
    }
    float mu  = sum * (1.f / 512.f);
    float var = sq * (1.f / 512.f) - mu * mu;
    float inv = rsqrtf(var + 1e-5f);

    float* orow = out + (size_t)row * DD;
    #pragma unroll
    for (int t = 0; t < 16; t++)
        orow[lane + 32 * t] = (tv[t] - mu) * inv;
}

// ---------------------------------------------------------------------------
extern "C" void kernel_launch(void* const* d_in, const int* in_sizes, int n_in,
                              void* d_out, int out_size)
{
    const float* x  = (const float*)d_in[0];
    const float* cw = (const float*)d_in[1];
    const float* cb = (const float*)d_in[2];
    const float* fw = (const float*)d_in[3];
    const float* fb = (const float*)d_in[4];
    float* out = (float*)d_out;

    // attention kernel needs ~66.6 KB dynamic smem
    const int attn_smem = (64 * 64 + 64 * 64 + 64 * 65 + 64 * 64 + 3 * 64) * 4;
    cudaFuncSetAttribute(attn_kernel,
                         cudaFuncAttributeMaxDynamicSharedMemorySize, attn_smem);

    dim3 cgrid(LL / 128, OC / 128, BB);
    conv_kernel<<<cgrid, 256>>>(x, cw, cb);

    dim3 agrid(LL / 64, HEADS, BB);
    attn_kernel<<<agrid, 256, attn_smem>>>();

    dim3 fgrid((BB * LL) / 64, DD / 64);
    fc_kernel<<<fgrid, 256>>>(fw, fb);

    ln_kernel<<<(BB * LL) / 8, 256>>>(x, out);
}

// round 3
// speedup vs baseline: 1.5129x; 1.5129x over previous
#include <cuda_runtime.h>
#include <cstdint>
#include <math.h>

#define HEADS 8
#define HD    64
#define BB    2
#define LL    2048
#define DD    512
#define OC    1536   // 3*HEADS*HD

// Scratch (device globals — no allocations allowed)
__device__ float g_qkv [BB * OC * LL];   // conv+swish output, [b, c, l]
__device__ float g_newv[BB * LL * DD];   // attention output, [b, l, h*HD+d]
__device__ float g_fc  [BB * LL * DD];   // fc+swish output,  [b, l, d]
__device__ float g_wt  [3 * OC * DD];    // transposed conv weights [t][o][i], tf32-rounded

__device__ __forceinline__ float swishf(float v) {
    return v / (1.f + __expf(-v));
}
__device__ __forceinline__ float to_tf32(float x) {
    float r; asm("cvt.rna.tf32.f32 %0, %1;" : "=f"(r) : "f"(x)); return r;
}

// m16n8k8 tf32 mma: D(16x8,f32) += A(16x8,tf32,row) * B(8x8,tf32,col)
__device__ __forceinline__ void mma_tf32(float c[4], const uint32_t a[4], const uint32_t b[2]) {
    asm volatile(
        "mma.sync.aligned.m16n8k8.row.col.f32.tf32.tf32.f32 "
        "{%0,%1,%2,%3}, {%4,%5,%6,%7}, {%8,%9}, {%0,%1,%2,%3};"
        : "+f"(c[0]), "+f"(c[1]), "+f"(c[2]), "+f"(c[3])
        : "r"(a[0]), "r"(a[1]), "r"(a[2]), "r"(a[3]), "r"(b[0]), "r"(b[1]));
}

// ---------------------------------------------------------------------------
// Kernel 0: transpose conv weights to [t][o][i] with tf32 rounding.
// ---------------------------------------------------------------------------
__global__ void wprep_kernel(const float* __restrict__ w)
{
    int idx = blockIdx.x * 256 + threadIdx.x;
    if (idx < 3 * OC * DD) {
        int i   = idx & 511;
        int rem = idx >> 9;          // t*OC + o
        int o   = rem % OC;
        int t   = rem / OC;
        g_wt[idx] = to_tf32(w[(size_t)o * 1536 + i * 3 + t]);
    }
}

// ---------------------------------------------------------------------------
// Kernel 1 (mma.sync tf32): Conv1d(D->OC,k=3,pad=1)+bias+swish -> g_qkv[b][o][l]
// GEMM: y[o,l] = sum_t sum_i g_wt[t][o][i] * x[b, l+t-1, i]
// CTA tile 128(o) x 128(l); 8 warps in 2(M) x 4(N); warp tile 64x32;
// per warp 4x4 m16n8k8 tiles; K-chunks of 32.
// ---------------------------------------------------------------------------
__global__ void __launch_bounds__(256, 2) conv_mma_kernel(const float* __restrict__ x,
                                                          const float* __restrict__ bias)
{
    __shared__ float sA[128][36];   // [m(o)][k] padded: bank = (4g+tg) bijective
    __shared__ float sB[128][36];   // [n(l)][k]

    const int b   = blockIdx.z;
    const int l0  = blockIdx.x * 128;
    const int o0  = blockIdx.y * 128;
    const int tid = threadIdx.x;
    const int wid = tid >> 5;
    const int lane = tid & 31;
    const int g   = lane >> 2;      // group id (rows)
    const int tg  = lane & 3;       // thread in group (cols/k)
    const int wm  = wid & 1;        // warp M index (0..1)
    const int wn  = wid >> 1;       // warp N index (0..3)

    float acc[4][4][4];
    #pragma unroll
    for (int mi = 0; mi < 4; mi++)
        #pragma unroll
        for (int ni = 0; ni < 4; ni++)
            #pragma unroll
            for (int q = 0; q < 4; q++) acc[mi][ni][q] = 0.f;

    for (int c = 0; c < 48; c++) {
        const int t  = c >> 4;           // tap 0..2
        const int i0 = (c & 15) * 32;    // input-channel chunk

        // A: 128 rows(o) x 32 k, float4 per thread x4
        const float* wt = g_wt + ((size_t)t * OC + o0) * DD + i0;
        #pragma unroll
        for (int r = 0; r < 4; r++) {
            int idx = tid + r * 256;         // 0..1023
            int m   = idx >> 3;
            int kq  = (idx & 7) * 4;
            float4 v = *reinterpret_cast<const float4*>(&wt[(size_t)m * DD + kq]);
            *reinterpret_cast<float4*>(&sA[m][kq]) = v;
        }
        // B: 128 rows(l) x 32 k, shifted by tap, zero-pad edges, tf32 round
        #pragma unroll
        for (int r = 0; r < 4; r++) {
            int idx = tid + r * 256;
            int n   = idx >> 3;
            int kq  = (idx & 7) * 4;
            int l   = l0 + n + t - 1;
            float4 v = make_float4(0.f, 0.f, 0.f, 0.f);
            if (l >= 0 && l < LL)
                v = *reinterpret_cast<const float4*>(&x[((size_t)(b * LL + l)) * DD + i0 + kq]);
            v.x = to_tf32(v.x); v.y = to_tf32(v.y); v.z = to_tf32(v.z); v.w = to_tf32(v.w);
            *reinterpret_cast<float4*>(&sB[n][kq]) = v;
        }
        __syncthreads();

        #pragma unroll
        for (int ks = 0; ks < 4; ks++) {
            const int k0 = ks * 8;
            uint32_t af[4][4], bf[4][2];
            #pragma unroll
            for (int mi = 0; mi < 4; mi++) {
                int m = wm * 64 + mi * 16;
                af[mi][0] = __float_as_uint(sA[m + g    ][k0 + tg    ]);
                af[mi][1] = __float_as_uint(sA[m + g + 8][k0 + tg    ]);
                af[mi][2] = __float_as_uint(sA[m + g    ][k0 + tg + 4]);
                af[mi][3] = __float_as_uint(sA[m + g + 8][k0 + tg + 4]);
            }
            #pragma unroll
            for (int ni = 0; ni < 4; ni++) {
                int n = wn * 32 + ni * 8;
                bf[ni][0] = __float_as_uint(sB[n + g][k0 + tg    ]);
                bf[ni][1] = __float_as_uint(sB[n + g][k0 + tg + 4]);
            }
            #pragma unroll
            for (int mi = 0; mi < 4; mi++)
                #pragma unroll
                for (int ni = 0; ni < 4; ni++)
                    mma_tf32(acc[mi][ni], af[mi], bf[ni]);
        }
        __syncthreads();
    }

    // Epilogue: bias + swish -> g_qkv[b][o][l]
    #pragma unroll
    for (int mi = 0; mi < 4; mi++) {
        int o_lo = o0 + wm * 64 + mi * 16 + g;
        int o_hi = o_lo + 8;
        float b_lo = bias[o_lo], b_hi = bias[o_hi];
        float* row_lo = g_qkv + ((size_t)b * OC + o_lo) * LL;
        float* row_hi = g_qkv + ((size_t)b * OC + o_hi) * LL;
        #pragma unroll
        for (int ni = 0; ni < 4; ni++) {
            int l = l0 + wn * 32 + ni * 8 + 2 * tg;
            float2 v0, v1;
            v0.x = swishf(acc[mi][ni][0] + b_lo);
            v0.y = swishf(acc[mi][ni][1] + b_lo);
            v1.x = swishf(acc[mi][ni][2] + b_hi);
            v1.y = swishf(acc[mi][ni][3] + b_hi);
            *reinterpret_cast<float2*>(&row_lo[l]) = v0;
            *reinterpret_cast<float2*>(&row_hi[l]) = v1;
        }
    }
}

// ---------------------------------------------------------------------------
// Kernel 2: flash-style attention per (b, h, 64-row tile). (fp32 FFMA)
// ---------------------------------------------------------------------------
__global__ void attn_kernel()
{
    extern __shared__ float sm[];
    float* sQ = sm;                 // [64][64]  (d, w)
    float* sK = sQ + 64 * 64;       // [64][64]  (d, m)
    float* sV = sK + 64 * 64;       // [64][65]  (d, m)  padded
    float* sP = sV + 64 * 65;       // [64][64]  (w, m)
    float* sM = sP + 64 * 64;       // [64]
    float* sL = sM + 64;            // [64]
    float* sS = sL + 64;            // [64] rescale factors

    const int b  = blockIdx.z;
    const int h  = blockIdx.y;
    const int w0 = blockIdx.x * 64;
    const int tid = threadIdx.x;
    const int ty = tid >> 4;
    const int tx = tid & 15;

    const float scale = rsqrtf((float)LL);
    const float* qbase = g_qkv + ((size_t)b * OC + h * 192) * LL;

    for (int idx = tid; idx < 4096; idx += 256) {
        int d = idx >> 6, ww = idx & 63;
        sQ[d * 64 + ww] = qbase[(size_t)d * LL + w0 + ww] * scale;
    }
    if (tid < 64) { sM[tid] = -1e30f; sL[tid] = 0.f; }

    float o_acc[4][4];
    #pragma unroll
    for (int i = 0; i < 4; i++)
        #pragma unroll
        for (int j = 0; j < 4; j++) o_acc[i][j] = 0.f;

    __syncthreads();

    for (int m0 = 0; m0 < LL; m0 += 64) {
        for (int idx = tid; idx < 4096; idx += 256) {
            int d = idx >> 6, mm = idx & 63;
            sK[d * 64 + mm] = qbase[(size_t)(64 + d) * LL + m0 + mm];
            sV[d * 65 + mm] = qbase[(size_t)(128 + d) * LL + m0 + mm];
        }
        __syncthreads();

        float sfr[4][4];
        #pragma unroll
        for (int i = 0; i < 4; i++)
            #pragma unroll
            for (int j = 0; j < 4; j++) sfr[i][j] = 0.f;
        for (int d = 0; d < 64; d++) {
            float qf[4], kf[4];
            #pragma unroll
            for (int i = 0; i < 4; i++) qf[i] = sQ[d * 64 + ty + 16 * i];
            #pragma unroll
            for (int j = 0; j < 4; j++) kf[j] = sK[d * 64 + tx + 16 * j];
            #pragma unroll
            for (int i = 0; i < 4; i++)
                #pragma unroll
                for (int j = 0; j < 4; j++) sfr[i][j] += qf[i] * kf[j];
        }
        #pragma unroll
        for (int i = 0; i < 4; i++)
            #pragma unroll
            for (int j = 0; j < 4; j++)
                sP[(ty + 16 * i) * 64 + tx + 16 * j] = sfr[i][j];
        __syncthreads();

        if (tid < 64) {
            int r = tid;
            float om = sM[r];
            float mx = om;
            for (int j = 0; j < 64; j++) mx = fmaxf(mx, sP[r * 64 + j]);
            float sc  = __expf(om - mx);
            float sum = 0.f;
            for (int j = 0; j < 64; j++) {
                float p = __expf(sP[r * 64 + j] - mx);
                sP[r * 64 + j] = p;
                sum += p;
            }
            sM[r] = mx;
            sL[r] = sL[r] * sc + sum;
            sS[r] = sc;
        }
        __syncthreads();

        #pragma unroll
        for (int i = 0; i < 4; i++) {
            float sc = sS[ty + 16 * i];
            #pragma unroll
            for (int j = 0; j < 4; j++) o_acc[i][j] *= sc;
        }
        for (int mm = 0; mm < 64; mm++) {
            float pf[4], vf[4];
            #pragma unroll
            for (int i = 0; i < 4; i++) pf[i] = sP[(ty + 16 * i) * 64 + mm];
            #pragma unroll
            for (int j = 0; j < 4; j++) vf[j] = sV[(tx + 16 * j) * 65 + mm];
            #pragma unroll
            for (int i = 0; i < 4; i++)
                #pragma unroll
                for (int j = 0; j < 4; j++) o_acc[i][j] += pf[i] * vf[j];
        }
        __syncthreads();
    }

    #pragma unroll
    for (int i = 0; i < 4; i++) {
        int ww = ty + 16 * i;
        float inv = 1.f / sL[ww];
        #pragma unroll
        for (int j = 0; j < 4; j++) {
            int d = tx + 16 * j;
            g_newv[((size_t)(b * LL) + w0 + ww) * DD + h * HD + d] = o_acc[i][j] * inv;
        }
    }
}

// ---------------------------------------------------------------------------
// Kernel 3 (mma.sync tf32): m = swish(new_v @ fc_w^T + fc_b) -> g_fc.
// GEMM M=4096(rows bl), N=512, K=512. Same microkernel as conv.
// ---------------------------------------------------------------------------
__global__ void __launch_bounds__(256, 2) fc_mma_kernel(const float* __restrict__ fw,
                                                        const float* __restrict__ fb)
{
    __shared__ float sA[128][36];   // [m][k]
    __shared__ float sB[128][36];   // [n][k]

    const int m0  = blockIdx.x * 128;
    const int n0  = blockIdx.y * 128;
    const int tid = threadIdx.x;
    const int wid = tid >> 5;
    const int lane = tid & 31;
    const int g   = lane >> 2;
    const int tg  = lane & 3;
    const int wm  = wid & 1;
    const int wn  = wid >> 1;

    float acc[4][4][4];
    #pragma unroll
    for (int mi = 0; mi < 4; mi++)
        #pragma unroll
        for (int ni = 0; ni < 4; ni++)
            #pragma unroll
            for (int q = 0; q < 4; q++) acc[mi][ni][q] = 0.f;

    for (int c = 0; c < 16; c++) {
        const int k0g = c * 32;
        #pragma unroll
        for (int r = 0; r < 4; r++) {
            int idx = tid + r * 256;
            int m   = idx >> 3;
            int kq  = (idx & 7) * 4;
            float4 v = *reinterpret_cast<const float4*>(&g_newv[(size_t)(m0 + m) * DD + k0g + kq]);
            v.x = to_tf32(v.x); v.y = to_tf32(v.y); v.z = to_tf32(v.z); v.w = to_tf32(v.w);
            *reinterpret_cast<float4*>(&sA[m][kq]) = v;
        }
        #pragma unroll
        for (int r = 0; r < 4; r++) {
            int idx = tid + r * 256;
            int n   = idx >> 3;
            int kq  = (idx & 7) * 4;
            float4 v = *reinterpret_cast<const float4*>(&fw[(size_t)(n0 + n) * DD + k0g + kq]);
            v.x = to_tf32(v.x); v.y = to_tf32(v.y); v.z = to_tf32(v.z); v.w = to_tf32(v.w);
            *reinterpret_cast<float4*>(&sB[n][kq]) = v;
        }
        __syncthreads();

        #pragma unroll
        for (int ks = 0; ks < 4; ks++) {
            const int k0 = ks * 8;
            uint32_t af[4][4], bf[4][2];
            #pragma unroll
            for (int mi = 0; mi < 4; mi++) {
                int m = wm * 64 + mi * 16;
                af[mi][0] = __float_as_uint(sA[m + g    ][k0 + tg    ]);
                af[mi][1] = __float_as_uint(sA[m + g + 8][k0 + tg    ]);
                af[mi][2] = __float_as_uint(sA[m + g    ][k0 + tg + 4]);
                af[mi][3] = __float_as_uint(sA[m + g + 8][k0 + tg + 4]);
            }
            #pragma unroll
            for (int ni = 0; ni < 4; ni++) {
                int n = wn * 32 + ni * 8;
                bf[ni][0] = __float_as_uint(sB[n + g][k0 + tg    ]);
                bf[ni][1] = __float_as_uint(sB[n + g][k0 + tg + 4]);
            }
            #pragma unroll
            for (int mi = 0; mi < 4; mi++)
                #pragma unroll
                for (int ni = 0; ni < 4; ni++)
                    mma_tf32(acc[mi][ni], af[mi], bf[ni]);
        }
        __syncthreads();
    }

    #pragma unroll
    for (int mi = 0; mi < 4; mi++) {
        int m_lo = m0 + wm * 64 + mi * 16 + g;
        int m_hi = m_lo + 8;
        #pragma unroll
        for (int ni = 0; ni < 4; ni++) {
            int n = n0 + wn * 32 + ni * 8 + 2 * tg;
            float b0 = fb[n], b1 = fb[n + 1];
            float2 v0, v1;
            v0.x = swishf(acc[mi][ni][0] + b0);
            v0.y = swishf(acc[mi][ni][1] + b1);
            v1.x = swishf(acc[mi][ni][2] + b0);
            v1.y = swishf(acc[mi][ni][3] + b1);
            *reinterpret_cast<float2*>(&g_fc[(size_t)m_lo * DD + n]) = v0;
            *reinterpret_cast<float2*>(&g_fc[(size_t)m_hi * DD + n]) = v1;
        }
    }
}

// ---------------------------------------------------------------------------
// Kernel 4: out = layer_norm(2*x + g_fc). One warp per row of 512.
// ---------------------------------------------------------------------------
__global__ void ln_kernel(const float* __restrict__ x,
                          float* __restrict__ out)
{
    const int row  = blockIdx.x * 8 + (threadIdx.x >> 5);
    const int lane = threadIdx.x & 31;
    const float* mrow = g_fc + (size_t)row * DD;
    const float* xrow = x    + (size_t)row * DD;

    float tv[16];
    float sum = 0.f, sq = 0.f;
    #pragma unroll
    for (int t = 0; t < 16; t++) {
        int d = lane + 32 * t;
        float v = 2.f * xrow[d] + mrow[d];
        tv[t] = v;
        sum += v;
        sq  += v * v;
    }
    #pragma unroll
    for (int off = 16; off >= 1; off >>= 1) {
        sum += __shfl_xor_sync(0xffffffff, sum, off);
        sq  += __shfl_xor_sync(0xffffffff, sq,  off);
    }
    float mu  = sum * (1.f / 512.f);
    float var = sq * (1.f / 512.f) - mu * mu;
    float inv = rsqrtf(var + 1e-5f);

    float* orow = out + (size_t)row * DD;
    #pragma unroll
    for (int t = 0; t < 16; t++)
        orow[lane + 32 * t] = (tv[t] - mu) * inv;
}

// ---------------------------------------------------------------------------
extern "C" void kernel_launch(void* const* d_in, const int* in_sizes, int n_in,
                              void* d_out, int out_size)
{
    const float* x  = (const float*)d_in[0];
    const float* cw = (const float*)d_in[1];
    const float* cb = (const float*)d_in[2];
    const float* fw = (const float*)d_in[3];
    const float* fb = (const float*)d_in[4];
    float* out = (float*)d_out;

    const int attn_smem = (64 * 64 + 64 * 64 + 64 * 65 + 64 * 64 + 3 * 64) * 4;
    cudaFuncSetAttribute(attn_kernel,
                         cudaFuncAttributeMaxDynamicSharedMemorySize, attn_smem);

    // 0) transpose + tf32-round weights
    wprep_kernel<<<(3 * OC * DD + 255) / 256, 256>>>(cw);

    // 1) conv+swish via mma.sync tf32
    dim3 cgrid(LL / 128, OC / 128, BB);
    conv_mma_kernel<<<cgrid, 256>>>(x, cb);

    // 2) attention (fp32)
    dim3 agrid(LL / 64, HEADS, BB);
    attn_kernel<<<agrid, 256, attn_smem>>>();

    // 3) fc + swish via mma.sync tf32
    dim3 fgrid((BB * LL) / 128, DD / 128);
    fc_mma_kernel<<<fgrid, 256>>>(fw, fb);

    // 4) residual + layernorm
    ln_kernel<<<(BB * LL) / 8, 256>>>(x, out);
}

// round 6
// speedup vs baseline: 4.0715x; 2.6911x over previous
#include <cuda_runtime.h>
#include <cstdint>
#include <math.h>

#define HEADS 8
#define HD    64
#define BB    2
#define LL    2048
#define DD    512
#define OC    1536   // 3*HEADS*HD

// Scratch (device globals — no allocations allowed)
__device__ float g_qkv [BB * OC * LL];   // conv+swish output, [b, c, l]
__device__ float g_newv[BB * LL * DD];   // attention output, [b, l, h*HD+d]
__device__ float g_fc  [BB * LL * DD];   // fc+swish output,  [b, l, d]
__device__ float g_wt  [3 * OC * DD];    // transposed conv weights [t][o][i], tf32-rounded

__device__ __forceinline__ float swishf(float v) {
    return v / (1.f + __expf(-v));
}
__device__ __forceinline__ float to_tf32(float x) {
    float r; asm("cvt.rna.tf32.f32 %0, %1;" : "=f"(r) : "f"(x)); return r;
}

// m16n8k8 tf32 mma: D(16x8,f32) += A(16x8,tf32,row) * B(8x8,tf32,col)
__device__ __forceinline__ void mma_tf32(float c[4], const uint32_t a[4], const uint32_t b[2]) {
    asm volatile(
        "mma.sync.aligned.m16n8k8.row.col.f32.tf32.tf32.f32 "
        "{%0,%1,%2,%3}, {%4,%5,%6,%7}, {%8,%9}, {%0,%1,%2,%3};"
        : "+f"(c[0]), "+f"(c[1]), "+f"(c[2]), "+f"(c[3])
        : "r"(a[0]), "r"(a[1]), "r"(a[2]), "r"(a[3]), "r"(b[0]), "r"(b[1]));
}

// ---------------------------------------------------------------------------
// Kernel 0: transpose conv weights to [t][o][i] with tf32 rounding.
// ---------------------------------------------------------------------------
__global__ void wprep_kernel(const float* __restrict__ w)
{
    int idx = blockIdx.x * 256 + threadIdx.x;
    if (idx < 3 * OC * DD) {
        int i   = idx & 511;
        int rem = idx >> 9;          // t*OC + o
        int o   = rem % OC;
        int t   = rem / OC;
        g_wt[idx] = to_tf32(w[(size_t)o * 1536 + i * 3 + t]);
    }
}

// ---------------------------------------------------------------------------
// Kernel 1 (mma.sync tf32): Conv1d(D->OC,k=3,pad=1)+bias+swish -> g_qkv[b][o][l]
// ---------------------------------------------------------------------------
__global__ void __launch_bounds__(256, 2) conv_mma_kernel(const float* __restrict__ x,
                                                          const float* __restrict__ bias)
{
    __shared__ float sA[128][36];   // [m(o)][k] padded: bank = (4g+tg) bijective
    __shared__ float sB[128][36];   // [n(l)][k]

    const int b   = blockIdx.z;
    const int l0  = blockIdx.x * 128;
    const int o0  = blockIdx.y * 128;
    const int tid = threadIdx.x;
    const int wid = tid >> 5;
    const int lane = tid & 31;
    const int g   = lane >> 2;
    const int tg  = lane & 3;
    const int wm  = wid & 1;
    const int wn  = wid >> 1;

    float acc[4][4][4];
    #pragma unroll
    for (int mi = 0; mi < 4; mi++)
        #pragma unroll
        for (int ni = 0; ni < 4; ni++)
            #pragma unroll
            for (int q = 0; q < 4; q++) acc[mi][ni][q] = 0.f;

    for (int c = 0; c < 48; c++) {
        const int t  = c >> 4;
        const int i0 = (c & 15) * 32;

        const float* wt = g_wt + ((size_t)t * OC + o0) * DD + i0;
        #pragma unroll
        for (int r = 0; r < 4; r++) {
            int idx = tid + r * 256;
            int m   = idx >> 3;
            int kq  = (idx & 7) * 4;
            float4 v = *reinterpret_cast<const float4*>(&wt[(size_t)m * DD + kq]);
            *reinterpret_cast<float4*>(&sA[m][kq]) = v;
        }
        #pragma unroll
        for (int r = 0; r < 4; r++) {
            int idx = tid + r * 256;
            int n   = idx >> 3;
            int kq  = (idx & 7) * 4;
            int l   = l0 + n + t - 1;
            float4 v = make_float4(0.f, 0.f, 0.f, 0.f);
            if (l >= 0 && l < LL)
                v = *reinterpret_cast<const float4*>(&x[((size_t)(b * LL + l)) * DD + i0 + kq]);
            v.x = to_tf32(v.x); v.y = to_tf32(v.y); v.z = to_tf32(v.z); v.w = to_tf32(v.w);
            *reinterpret_cast<float4*>(&sB[n][kq]) = v;
        }
        __syncthreads();

        #pragma unroll
        for (int ks = 0; ks < 4; ks++) {
            const int k0 = ks * 8;
            uint32_t af[4][4], bf[4][2];
            #pragma unroll
            for (int mi = 0; mi < 4; mi++) {
                int m = wm * 64 + mi * 16;
                af[mi][0] = __float_as_uint(sA[m + g    ][k0 + tg    ]);
                af[mi][1] = __float_as_uint(sA[m + g + 8][k0 + tg    ]);
                af[mi][2] = __float_as_uint(sA[m + g    ][k0 + tg + 4]);
                af[mi][3] = __float_as_uint(sA[m + g + 8][k0 + tg + 4]);
            }
            #pragma unroll
            for (int ni = 0; ni < 4; ni++) {
                int n = wn * 32 + ni * 8;
                bf[ni][0] = __float_as_uint(sB[n + g][k0 + tg    ]);
                bf[ni][1] = __float_as_uint(sB[n + g][k0 + tg + 4]);
            }
            #pragma unroll
            for (int mi = 0; mi < 4; mi++)
                #pragma unroll
                for (int ni = 0; ni < 4; ni++)
                    mma_tf32(acc[mi][ni], af[mi], bf[ni]);
        }
        __syncthreads();
    }

    #pragma unroll
    for (int mi = 0; mi < 4; mi++) {
        int o_lo = o0 + wm * 64 + mi * 16 + g;
        int o_hi = o_lo + 8;
        float b_lo = bias[o_lo], b_hi = bias[o_hi];
        float* row_lo = g_qkv + ((size_t)b * OC + o_lo) * LL;
        float* row_hi = g_qkv + ((size_t)b * OC + o_hi) * LL;
        #pragma unroll
        for (int ni = 0; ni < 4; ni++) {
            int l = l0 + wn * 32 + ni * 8 + 2 * tg;
            float2 v0, v1;
            v0.x = swishf(acc[mi][ni][0] + b_lo);
            v0.y = swishf(acc[mi][ni][1] + b_lo);
            v1.x = swishf(acc[mi][ni][2] + b_hi);
            v1.y = swishf(acc[mi][ni][3] + b_hi);
            *reinterpret_cast<float2*>(&row_lo[l]) = v0;
            *reinterpret_cast<float2*>(&row_hi[l]) = v1;
        }
    }
}

// ---------------------------------------------------------------------------
// Kernel 2 (mma.sync tf32): flash attention, CTA = (b, h, 128-row w tile).
// Loop over m-chunks of 64. S=Q^T K and O += P V^T both via m16n8k8 tf32.
// 8 warps: wm=wid&3 (32 rows each), wn=wid>>2 (32 cols each).
// Smem stride 68: fragment LDS bank = (4g+tg) mod 32, bijective -> deg 1.
// ---------------------------------------------------------------------------
#define AST 68
#define ATTN_SMEM ((128*AST + 64*AST + 64*AST + 128*AST + 3*128) * 4)

__global__ void __launch_bounds__(256) attn_mma_kernel()
{
    extern __shared__ float sm[];
    float* sQ = sm;                    // [128][AST]  (w, d)  Q^T, pre-scaled
    float* sK = sQ + 128 * AST;        // [64][AST]   (m, d)  K^T
    float* sV = sK + 64 * AST;         // [64][AST]   (dd, m) natural
    float* sP = sV + 64 * AST;         // [128][AST]  (w, m)  scores/probs
    float* sM = sP + 128 * AST;        // [128] running max
    float* sL = sM + 128;              // [128] running denom
    float* sS = sL + 128;              // [128] rescale factor

    const int b   = blockIdx.z;
    const int h   = blockIdx.y;
    const int w0  = blockIdx.x * 128;
    const int tid = threadIdx.x;
    const int wid = tid >> 5;
    const int lane = tid & 31;
    const int g   = lane >> 2;
    const int tg  = lane & 3;
    const int wm  = wid & 3;        // 0..3 -> 32 w-rows each
    const int wn  = wid >> 2;       // 0..1 -> 32 cols each

    const float scale = rsqrtf((float)LL);
    const float* qbase = g_qkv + ((size_t)b * OC + h * 192) * LL;
    const float* kbase = qbase + (size_t)64 * LL;
    const float* vbase = qbase + (size_t)128 * LL;

    // Load Q tile [128 w][64 d], transposed from [d][l], pre-scaled + tf32
    #pragma unroll
    for (int r = 0; r < 32; r++) {
        int idx = tid + r * 256;
        int ww  = idx & 127;
        int d   = idx >> 7;
        sQ[ww * AST + d] = to_tf32(qbase[(size_t)d * LL + w0 + ww] * scale);
    }
    if (tid < 128) { sM[tid] = -1e30f; sL[tid] = 0.f; }

    float acc_o[2][4][4];
    #pragma unroll
    for (int mi = 0; mi < 2; mi++)
        #pragma unroll
        for (int ni = 0; ni < 4; ni++)
            #pragma unroll
            for (int q = 0; q < 4; q++) acc_o[mi][ni][q] = 0.f;

    __syncthreads();

    for (int m0 = 0; m0 < LL; m0 += 64) {
        // Load K (transposed -> [m][d]) and V (natural -> [dd][m])
        #pragma unroll
        for (int r = 0; r < 16; r++) {
            int idx = tid + r * 256;
            int mm  = idx & 63;
            int dd  = idx >> 6;
            sK[mm * AST + dd] = to_tf32(kbase[(size_t)dd * LL + m0 + mm]);
            sV[dd * AST + mm] = to_tf32(vbase[(size_t)dd * LL + m0 + mm]);
        }
        __syncthreads();

        // GEMM1: S[128 w][64 m] = Q * K^T, k = d = 64
        float acc_s[2][4][4];
        #pragma unroll
        for (int mi = 0; mi < 2; mi++)
            #pragma unroll
            for (int ni = 0; ni < 4; ni++)
                #pragma unroll
                for (int q = 0; q < 4; q++) acc_s[mi][ni][q] = 0.f;

        #pragma unroll
        for (int ks = 0; ks < 8; ks++) {
            const int k0 = ks * 8;
            uint32_t af[2][4], bf[4][2];
            #pragma unroll
            for (int mi = 0; mi < 2; mi++) {
                int m = wm * 32 + mi * 16;
                af[mi][0] = __float_as_uint(sQ[(m + g    ) * AST + k0 + tg    ]);
                af[mi][1] = __float_as_uint(sQ[(m + g + 8) * AST + k0 + tg    ]);
                af[mi][2] = __float_as_uint(sQ[(m + g    ) * AST + k0 + tg + 4]);
                af[mi][3] = __float_as_uint(sQ[(m + g + 8) * AST + k0 + tg + 4]);
            }
            #pragma unroll
            for (int ni = 0; ni < 4; ni++) {
                int n = wn * 32 + ni * 8;
                bf[ni][0] = __float_as_uint(sK[(n + g) * AST + k0 + tg    ]);
                bf[ni][1] = __float_as_uint(sK[(n + g) * AST + k0 + tg + 4]);
            }
            #pragma unroll
            for (int mi = 0; mi < 2; mi++)
                #pragma unroll
                for (int ni = 0; ni < 4; ni++)
                    mma_tf32(acc_s[mi][ni], af[mi], bf[ni]);
        }

        // Write S to sP
        #pragma unroll
        for (int mi = 0; mi < 2; mi++) {
            int r_lo = wm * 32 + mi * 16 + g;
            int r_hi = r_lo + 8;
            #pragma unroll
            for (int ni = 0; ni < 4; ni++) {
                int cc = wn * 32 + ni * 8 + 2 * tg;
                *reinterpret_cast<float2*>(&sP[r_lo * AST + cc]) =
                    make_float2(acc_s[mi][ni][0], acc_s[mi][ni][1]);
                *reinterpret_cast<float2*>(&sP[r_hi * AST + cc]) =
                    make_float2(acc_s[mi][ni][2], acc_s[mi][ni][3]);
            }
        }
        __syncthreads();

        // Online softmax: 2 threads per row (adjacent lanes), 32 cols each
        {
            int row  = tid >> 1;
            int half = tid & 1;
            float* pr = sP + row * AST + half * 32;
            float om = sM[row];
            float mx = -1e30f;
            #pragma unroll
            for (int j = 0; j < 32; j++) mx = fmaxf(mx, pr[j]);
            mx = fmaxf(mx, __shfl_xor_sync(0xffffffff, mx, 1));
            mx = fmaxf(mx, om);
            float sum = 0.f;
            #pragma unroll
            for (int j = 0; j < 32; j++) {
                float p = __expf(pr[j] - mx);
                pr[j] = p;
                sum += p;
            }
            sum += __shfl_xor_sync(0xffffffff, sum, 1);
            if (half == 0) {
                float sc = __expf(om - mx);
                sM[row] = mx;
                sL[row] = sL[row] * sc + sum;
                sS[row] = sc;
            }
        }
        __syncthreads();

        // Rescale O accumulators, then GEMM2: O[128 w][64 dd] += P * V^T, k=m=64
        #pragma unroll
        for (int mi = 0; mi < 2; mi++) {
            int r_lo = wm * 32 + mi * 16 + g;
            float s0 = sS[r_lo], s1 = sS[r_lo + 8];
            #pragma unroll
            for (int ni = 0; ni < 4; ni++) {
                acc_o[mi][ni][0] *= s0; acc_o[mi][ni][1] *= s0;
                acc_o[mi][ni][2] *= s1; acc_o[mi][ni][3] *= s1;
            }
        }
        #pragma unroll
        for (int ks = 0; ks < 8; ks++) {
            const int k0 = ks * 8;
            uint32_t af[2][4], bf[4][2];
            #pragma unroll
            for (int mi = 0; mi < 2; mi++) {
                int m = wm * 32 + mi * 16;
                af[mi][0] = __float_as_uint(sP[(m + g    ) * AST + k0 + tg    ]);
                af[mi][1] = __float_as_uint(sP[(m + g + 8) * AST + k0 + tg    ]);
                af[mi][2] = __float_as_uint(sP[(m + g    ) * AST + k0 + tg + 4]);
                af[mi][3] = __float_as_uint(sP[(m + g + 8) * AST + k0 + tg + 4]);
            }
            #pragma unroll
            for (int ni = 0; ni < 4; ni++) {
                int n = wn * 32 + ni * 8;
                bf[ni][0] = __float_as_uint(sV[(n + g) * AST + k0 + tg    ]);
                bf[ni][1] = __float_as_uint(sV[(n + g) * AST + k0 + tg + 4]);
            }
            #pragma unroll
            for (int mi = 0; mi < 2; mi++)
                #pragma unroll
                for (int ni = 0; ni < 4; ni++)
                    mma_tf32(acc_o[mi][ni], af[mi], bf[ni]);
        }
        __syncthreads();
    }

    // Final: O /= L, write g_newv[b, w0+w, h*64+dd]
    #pragma unroll
    for (int mi = 0; mi < 2; mi++) {
        int r_lo = wm * 32 + mi * 16 + g;
        int r_hi = r_lo + 8;
        float inv0 = 1.f / sL[r_lo];
        float inv1 = 1.f / sL[r_hi];
        float* out_lo = g_newv + ((size_t)(b * LL) + w0 + r_lo) * DD + h * HD;
        float* out_hi = g_newv + ((size_t)(b * LL) + w0 + r_hi) * DD + h * HD;
        #pragma unroll
        for (int ni = 0; ni < 4; ni++) {
            int cc = wn * 32 + ni * 8 + 2 * tg;
            *reinterpret_cast<float2*>(&out_lo[cc]) =
                make_float2(acc_o[mi][ni][0] * inv0, acc_o[mi][ni][1] * inv0);
            *reinterpret_cast<float2*>(&out_hi[cc]) =
                make_float2(acc_o[mi][ni][2] * inv1, acc_o[mi][ni][3] * inv1);
        }
    }
}

// ---------------------------------------------------------------------------
// Kernel 3 (mma.sync tf32): m = swish(new_v @ fc_w^T + fc_b) -> g_fc.
// ---------------------------------------------------------------------------
__global__ void __launch_bounds__(256, 2) fc_mma_kernel(const float* __restrict__ fw,
                                                        const float* __restrict__ fb)
{
    __shared__ float sA[128][36];
    __shared__ float sB[128][36];

    const int m0  = blockIdx.x * 128;
    const int n0  = blockIdx.y * 128;
    const int tid = threadIdx.x;
    const int wid = tid >> 5;
    const int lane = tid & 31;
    const int g   = lane >> 2;
    const int tg  = lane & 3;
    const int wm  = wid & 1;
    const int wn  = wid >> 1;

    float acc[4][4][4];
    #pragma unroll
    for (int mi = 0; mi < 4; mi++)
        #pragma unroll
        for (int ni = 0; ni < 4; ni++)
            #pragma unroll
            for (int q = 0; q < 4; q++) acc[mi][ni][q] = 0.f;

    for (int c = 0; c < 16; c++) {
        const int k0g = c * 32;
        #pragma unroll
        for (int r = 0; r < 4; r++) {
            int idx = tid + r * 256;
            int m   = idx >> 3;
            int kq  = (idx & 7) * 4;
            float4 v = *reinterpret_cast<const float4*>(&g_newv[(size_t)(m0 + m) * DD + k0g + kq]);
            v.x = to_tf32(v.x); v.y = to_tf32(v.y); v.z = to_tf32(v.z); v.w = to_tf32(v.w);
            *reinterpret_cast<float4*>(&sA[m][kq]) = v;
        }
        #pragma unroll
        for (int r = 0; r < 4; r++) {
            int idx = tid + r * 256;
            int n   = idx >> 3;
            int kq  = (idx & 7) * 4;
            float4 v = *reinterpret_cast<const float4*>(&fw[(size_t)(n0 + n) * DD + k0g + kq]);
            v.x = to_tf32(v.x); v.y = to_tf32(v.y); v.z = to_tf32(v.z); v.w = to_tf32(v.w);
            *reinterpret_cast<float4*>(&sB[n][kq]) = v;
        }
        __syncthreads();

        #pragma unroll
        for (int ks = 0; ks < 4; ks++) {
            const int k0 = ks * 8;
            uint32_t af[4][4], bf[4][2];
            #pragma unroll
            for (int mi = 0; mi < 4; mi++) {
                int m = wm * 64 + mi * 16;
                af[mi][0] = __float_as_uint(sA[m + g    ][k0 + tg    ]);
                af[mi][1] = __float_as_uint(sA[m + g + 8][k0 + tg    ]);
                af[mi][2] = __float_as_uint(sA[m + g    ][k0 + tg + 4]);
                af[mi][3] = __float_as_uint(sA[m + g + 8][k0 + tg + 4]);
            }
            #pragma unroll
            for (int ni = 0; ni < 4; ni++) {
                int n = wn * 32 + ni * 8;
                bf[ni][0] = __float_as_uint(sB[n + g][k0 + tg    ]);
                bf[ni][1] = __float_as_uint(sB[n + g][k0 + tg + 4]);
            }
            #pragma unroll
            for (int mi = 0; mi < 4; mi++)
                #pragma unroll
                for (int ni = 0; ni < 4; ni++)
                    mma_tf32(acc[mi][ni], af[mi], bf[ni]);
        }
        __syncthreads();
    }

    #pragma unroll
    for (int mi = 0; mi < 4; mi++) {
        int m_lo = m0 + wm * 64 + mi * 16 + g;
        int m_hi = m_lo + 8;
        #pragma unroll
        for (int ni = 0; ni < 4; ni++) {
            int n = n0 + wn * 32 + ni * 8 + 2 * tg;
            float b0 = fb[n], b1 = fb[n + 1];
            float2 v0, v1;
            v0.x = swishf(acc[mi][ni][0] + b0);
            v0.y = swishf(acc[mi][ni][1] + b1);
            v1.x = swishf(acc[mi][ni][2] + b0);
            v1.y = swishf(acc[mi][ni][3] + b1);
            *reinterpret_cast<float2*>(&g_fc[(size_t)m_lo * DD + n]) = v0;
            *reinterpret_cast<float2*>(&g_fc[(size_t)m_hi * DD + n]) = v1;
        }
    }
}

// ---------------------------------------------------------------------------
// Kernel 4: out = layer_norm(2*x + g_fc). One warp per row of 512.
// ---------------------------------------------------------------------------
__global__ void ln_kernel(const float* __restrict__ x,
                          float* __restrict__ out)
{
    const int row  = blockIdx.x * 8 + (threadIdx.x >> 5);
    const int lane = threadIdx.x & 31;
    const float* mrow = g_fc + (size_t)row * DD;
    const float* xrow = x    + (size_t)row * DD;

    float tv[16];
    float sum = 0.f, sq = 0.f;
    #pragma unroll
    for (int t = 0; t < 16; t++) {
        int d = lane + 32 * t;
        float v = 2.f * xrow[d] + mrow[d];
        tv[t] = v;
        sum += v;
        sq  += v * v;
    }
    #pragma unroll
    for (int off = 16; off >= 1; off >>= 1) {
        sum += __shfl_xor_sync(0xffffffff, sum, off);
        sq  += __shfl_xor_sync(0xffffffff, sq,  off);
    }
    float mu  = sum * (1.f / 512.f);
    float var = sq * (1.f / 512.f) - mu * mu;
    float inv = rsqrtf(var + 1e-5f);

    float* orow = out + (size_t)row * DD;
    #pragma unroll
    for (int t = 0; t < 16; t++)
        orow[lane + 32 * t] = (tv[t] - mu) * inv;
}

// ---------------------------------------------------------------------------
extern "C" void kernel_launch(void* const* d_in, const int* in_sizes, int n_in,
                              void* d_out, int out_size)
{
    const float* x  = (const float*)d_in[0];
    const float* cw = (const float*)d_in[1];
    const float* cb = (const float*)d_in[2];
    const float* fw = (const float*)d_in[3];
    const float* fb = (const float*)d_in[4];
    float* out = (float*)d_out;

    cudaFuncSetAttribute(attn_mma_kernel,
                         cudaFuncAttributeMaxDynamicSharedMemorySize, ATTN_SMEM);

    // 0) transpose + tf32-round weights
    wprep_kernel<<<(3 * OC * DD + 255) / 256, 256>>>(cw);

    // 1) conv+swish via mma.sync tf32
    dim3 cgrid(LL / 128, OC / 128, BB);
    conv_mma_kernel<<<cgrid, 256>>>(x, cb);

    // 2) attention via mma.sync tf32
    dim3 agrid(LL / 128, HEADS, BB);
    attn_mma_kernel<<<agrid, 256, ATTN_SMEM>>>();

    // 3) fc + swish via mma.sync tf32
    dim3 fgrid((BB * LL) / 128, DD / 128);
    fc_mma_kernel<<<fgrid, 256>>>(fw, fb);

    // 4) residual + layernorm
    ln_kernel<<<(BB * LL) / 8, 256>>>(x, out);
}

// round 7
// speedup vs baseline: 4.7373x; 1.1635x over previous
#include <cuda_runtime.h>
#include <cstdint>
#include <math.h>

#define HEADS 8
#define HD    64
#define BB    2
#define LL    2048
#define DD    512
#define OC    1536   // 3*HEADS*HD

// Scratch (device globals — no allocations allowed)
__device__ float g_qkv [BB * OC * LL];   // conv+swish output, [b, c, l]
__device__ float g_newv[BB * LL * DD];   // attention output, [b, l, h*HD+d]
__device__ float g_fc  [BB * LL * DD];   // fc+swish output,  [b, l, d]
__device__ float g_wt  [3 * OC * DD];    // transposed conv weights [t][o][i], tf32-rounded

__device__ __forceinline__ float swishf(float v) {
    return v / (1.f + __expf(-v));
}
__device__ __forceinline__ float to_tf32(float x) {
    float r; asm("cvt.rna.tf32.f32 %0, %1;" : "=f"(r) : "f"(x)); return r;
}
__device__ __forceinline__ uint32_t smem_u32(const void* p) {
    return (uint32_t)__cvta_generic_to_shared(p);
}
__device__ __forceinline__ void cpa16(uint32_t dst, const void* src) {
    asm volatile("cp.async.cg.shared.global [%0], [%1], 16;" :: "r"(dst), "l"(src));
}
__device__ __forceinline__ void cpa16p(uint32_t dst, const void* src, bool pred) {
    int sz = pred ? 16 : 0;
    asm volatile("cp.async.cg.shared.global [%0], [%1], 16, %2;" :: "r"(dst), "l"(src), "r"(sz));
}
#define CPC()      asm volatile("cp.async.commit_group;" ::: "memory")
#define CP_WAIT0() asm volatile("cp.async.wait_group 0;" ::: "memory")
#define CP_WAIT1() asm volatile("cp.async.wait_group 1;" ::: "memory")

// m16n8k8 tf32 mma: D(16x8,f32) += A(16x8,tf32,row) * B(8x8,tf32,col)
__device__ __forceinline__ void mma_tf32(float c[4], const uint32_t a[4], const uint32_t b[2]) {
    asm volatile(
        "mma.sync.aligned.m16n8k8.row.col.f32.tf32.tf32.f32 "
        "{%0,%1,%2,%3}, {%4,%5,%6,%7}, {%8,%9}, {%0,%1,%2,%3};"
        : "+f"(c[0]), "+f"(c[1]), "+f"(c[2]), "+f"(c[3])
        : "r"(a[0]), "r"(a[1]), "r"(a[2]), "r"(a[3]), "r"(b[0]), "r"(b[1]));
}

// ---------------------------------------------------------------------------
// Kernel 0: transpose conv weights to [t][o][i] with tf32 rounding.
// ---------------------------------------------------------------------------
__global__ void wprep_kernel(const float* __restrict__ w)
{
    int idx = blockIdx.x * 256 + threadIdx.x;
    if (idx < 3 * OC * DD) {
        int i   = idx & 511;
        int rem = idx >> 9;          // t*OC + o
        int o   = rem % OC;
        int t   = rem / OC;
        g_wt[idx] = to_tf32(w[(size_t)o * 1536 + i * 3 + t]);
    }
}

// ---------------------------------------------------------------------------
// Kernel 1 (mma.sync tf32 + cp.async double buffer):
// Conv1d(D->OC,k=3,pad=1)+bias+swish -> g_qkv[b][o][l]
// smem: sA[2][128][36] | sB[2][128][36]  (dynamic, 72 KB)
// ---------------------------------------------------------------------------
#define CONV_SMEM (4 * 128 * 36 * 4)

__device__ __forceinline__ void conv_issue(float* dsm, int buf, int c, int b,
                                           int o0, int l0,
                                           const float* __restrict__ x, int tid)
{
    const int t  = c >> 4;
    const int i0 = (c & 15) * 32;
    const float* wt = g_wt + ((size_t)t * OC + o0) * DD + i0;
    float* sA = dsm + buf * 4608;
    float* sB = dsm + 9216 + buf * 4608;
    #pragma unroll
    for (int r = 0; r < 4; r++) {
        int idx = tid + r * 256;
        int m = idx >> 3, kq = (idx & 7) * 4;
        cpa16(smem_u32(&sA[m * 36 + kq]), wt + (size_t)m * DD + kq);
    }
    #pragma unroll
    for (int r = 0; r < 4; r++) {
        int idx = tid + r * 256;
        int n = idx >> 3, kq = (idx & 7) * 4;
        int l = l0 + n + t - 1;
        bool ok = (l >= 0) && (l < LL);
        const float* src = ok ? (x + ((size_t)(b * LL + l)) * DD + i0 + kq) : x;
        cpa16p(smem_u32(&sB[n * 36 + kq]), src, ok);
    }
}

__global__ void __launch_bounds__(256, 2) conv_mma_kernel(const float* __restrict__ x,
                                                          const float* __restrict__ bias)
{
    extern __shared__ float dsm[];

    const int b   = blockIdx.z;
    const int l0  = blockIdx.x * 128;
    const int o0  = blockIdx.y * 128;
    const int tid = threadIdx.x;
    const int wid = tid >> 5;
    const int lane = tid & 31;
    const int g   = lane >> 2;
    const int tg  = lane & 3;
    const int wm  = wid & 1;
    const int wn  = wid >> 1;

    float acc[4][4][4];
    #pragma unroll
    for (int mi = 0; mi < 4; mi++)
        #pragma unroll
        for (int ni = 0; ni < 4; ni++)
            #pragma unroll
            for (int q = 0; q < 4; q++) acc[mi][ni][q] = 0.f;

    conv_issue(dsm, 0, 0, b, o0, l0, x, tid);
    CPC();

    for (int c = 0; c < 48; c++) {
        const int cur = c & 1;
        if (c < 47) {
            conv_issue(dsm, cur ^ 1, c + 1, b, o0, l0, x, tid);
            CPC();
            CP_WAIT1();
        } else {
            CP_WAIT0();
        }
        __syncthreads();

        const float* A  = dsm + cur * 4608;
        const float* Bm = dsm + 9216 + cur * 4608;

        #pragma unroll
        for (int ks = 0; ks < 4; ks++) {
            const int k0 = ks * 8;
            uint32_t af[4][4], bf[4][2];
            #pragma unroll
            for (int mi = 0; mi < 4; mi++) {
                int m = wm * 64 + mi * 16;
                af[mi][0] = __float_as_uint(A[(m + g    ) * 36 + k0 + tg    ]);
                af[mi][1] = __float_as_uint(A[(m + g + 8) * 36 + k0 + tg    ]);
                af[mi][2] = __float_as_uint(A[(m + g    ) * 36 + k0 + tg + 4]);
                af[mi][3] = __float_as_uint(A[(m + g + 8) * 36 + k0 + tg + 4]);
            }
            #pragma unroll
            for (int ni = 0; ni < 4; ni++) {
                int n = wn * 32 + ni * 8;
                bf[ni][0] = __float_as_uint(Bm[(n + g) * 36 + k0 + tg    ]);
                bf[ni][1] = __float_as_uint(Bm[(n + g) * 36 + k0 + tg + 4]);
            }
            #pragma unroll
            for (int mi = 0; mi < 4; mi++)
                #pragma unroll
                for (int ni = 0; ni < 4; ni++)
                    mma_tf32(acc[mi][ni], af[mi], bf[ni]);
        }
        __syncthreads();
    }

    #pragma unroll
    for (int mi = 0; mi < 4; mi++) {
        int o_lo = o0 + wm * 64 + mi * 16 + g;
        int o_hi = o_lo + 8;
        float b_lo = bias[o_lo], b_hi = bias[o_hi];
        float* row_lo = g_qkv + ((size_t)b * OC + o_lo) * LL;
        float* row_hi = g_qkv + ((size_t)b * OC + o_hi) * LL;
        #pragma unroll
        for (int ni = 0; ni < 4; ni++) {
            int l = l0 + wn * 32 + ni * 8 + 2 * tg;
            float2 v0, v1;
            v0.x = swishf(acc[mi][ni][0] + b_lo);
            v0.y = swishf(acc[mi][ni][1] + b_lo);
            v1.x = swishf(acc[mi][ni][2] + b_hi);
            v1.y = swishf(acc[mi][ni][3] + b_hi);
            *reinterpret_cast<float2*>(&row_lo[l]) = v0;
            *reinterpret_cast<float2*>(&row_hi[l]) = v1;
        }
    }
}

// ---------------------------------------------------------------------------
// Kernel 2 (mma.sync tf32 + cp.async): flash attention.
// CTA = (b, h, 256-row w tile), 512 threads (16 warps: wm 0..7 x wn 0..1).
// Q stored [d][w] (k-major), K [d][m] (k-major), V [dd][m]; all cp.async
// coalesced. K/V double-buffered over 32 m-chunks of 64.
// Strides: QST=264, KST=72 (≡8 mod 32 -> banks 8tg+g bijective);
//          VST=68, PST=68 (≡4 mod 32 -> banks 4g+tg bijective).
// ---------------------------------------------------------------------------
#define QST 264
#define KST 72
#define VST 68
#define PST 68
#define ATTN_SMEM ((64*QST + 2*64*KST + 2*64*VST + 256*PST + 3*256) * 4)

__device__ __forceinline__ void attn_issue_kv(float* sK, float* sV, int buf,
                                              const float* __restrict__ kbase,
                                              const float* __restrict__ vbase,
                                              int m0, int tid)
{
    float* k = sK + buf * 64 * KST;
    float* v = sV + buf * 64 * VST;
    #pragma unroll
    for (int r = 0; r < 2; r++) {
        int idx = tid + r * 512;
        int dd = idx >> 4;
        int ms = (idx & 15) * 4;
        cpa16(smem_u32(&k[dd * KST + ms]), kbase + (size_t)dd * LL + m0 + ms);
    }
    #pragma unroll
    for (int r = 0; r < 2; r++) {
        int idx = tid + r * 512;
        int dd = idx >> 4;
        int ms = (idx & 15) * 4;
        cpa16(smem_u32(&v[dd * VST + ms]), vbase + (size_t)dd * LL + m0 + ms);
    }
}

__global__ void __launch_bounds__(512, 1) attn_mma_kernel()
{
    extern __shared__ float dsm[];
    float* sQ = dsm;                       // [64][QST]   (d, w)
    float* sK = sQ + 64 * QST;             // [2][64][KST] (d, m)
    float* sV = sK + 2 * 64 * KST;         // [2][64][VST] (dd, m)
    float* sP = sV + 2 * 64 * VST;         // [256][PST]  (w, m)
    float* sM = sP + 256 * PST;            // [256]
    float* sL = sM + 256;                  // [256]
    float* sS = sL + 256;                  // [256]

    const int b   = blockIdx.z;
    const int h   = blockIdx.y;
    const int w0  = blockIdx.x * 256;
    const int tid = threadIdx.x;
    const int wid = tid >> 5;
    const int lane = tid & 31;
    const int g   = lane >> 2;
    const int tg  = lane & 3;
    const int wm  = wid & 7;        // 0..7 -> 32 w-rows each
    const int wn  = wid >> 3;       // 0..1 -> 32 cols each

    const float scale = rsqrtf((float)LL);
    const float* qbase = g_qkv + ((size_t)b * OC + h * 192) * LL;
    const float* kbase = qbase + (size_t)64 * LL;
    const float* vbase = qbase + (size_t)128 * LL;

    // Q tile [64 d][256 w] via cp.async (coalesced)
    #pragma unroll
    for (int r = 0; r < 8; r++) {
        int idx = tid + r * 512;
        int dd = idx >> 6;
        int ws = (idx & 63) * 4;
        cpa16(smem_u32(&sQ[dd * QST + ws]), qbase + (size_t)dd * LL + w0 + ws);
    }
    attn_issue_kv(sK, sV, 0, kbase, vbase, 0, tid);
    CPC();

    if (tid < 256) { sM[tid] = -1e30f; sL[tid] = 0.f; }

    float acc_o[2][4][4];
    #pragma unroll
    for (int mi = 0; mi < 2; mi++)
        #pragma unroll
        for (int ni = 0; ni < 4; ni++)
            #pragma unroll
            for (int q = 0; q < 4; q++) acc_o[mi][ni][q] = 0.f;

    CP_WAIT0();
    __syncthreads();

    for (int c = 0; c < 32; c++) {
        const int cur = c & 1;
        if (c < 31) {
            attn_issue_kv(sK, sV, cur ^ 1, kbase, vbase, (c + 1) * 64, tid);
            CPC();
        }
        const float* K = sK + cur * 64 * KST;
        const float* V = sV + cur * 64 * VST;

        // GEMM1: S[256 w][64 m] = Q^T K (k = d = 64)
        float acc_s[2][4][4];
        #pragma unroll
        for (int mi = 0; mi < 2; mi++)
            #pragma unroll
            for (int ni = 0; ni < 4; ni++)
                #pragma unroll
                for (int q = 0; q < 4; q++) acc_s[mi][ni][q] = 0.f;

        #pragma unroll
        for (int ks = 0; ks < 8; ks++) {
            const int k0 = ks * 8;
            uint32_t af[2][4], bf[4][2];
            #pragma unroll
            for (int mi = 0; mi < 2; mi++) {
                int m = wm * 32 + mi * 16 + g;
                af[mi][0] = __float_as_uint(sQ[(k0 + tg    ) * QST + m    ]);
                af[mi][1] = __float_as_uint(sQ[(k0 + tg    ) * QST + m + 8]);
                af[mi][2] = __float_as_uint(sQ[(k0 + tg + 4) * QST + m    ]);
                af[mi][3] = __float_as_uint(sQ[(k0 + tg + 4) * QST + m + 8]);
            }
            #pragma unroll
            for (int ni = 0; ni < 4; ni++) {
                int n = wn * 32 + ni * 8 + g;
                bf[ni][0] = __float_as_uint(K[(k0 + tg    ) * KST + n]);
                bf[ni][1] = __float_as_uint(K[(k0 + tg + 4) * KST + n]);
            }
            #pragma unroll
            for (int mi = 0; mi < 2; mi++)
                #pragma unroll
                for (int ni = 0; ni < 4; ni++)
                    mma_tf32(acc_s[mi][ni], af[mi], bf[ni]);
        }

        // Write S * scale to sP
        #pragma unroll
        for (int mi = 0; mi < 2; mi++) {
            int r_lo = wm * 32 + mi * 16 + g;
            int r_hi = r_lo + 8;
            #pragma unroll
            for (int ni = 0; ni < 4; ni++) {
                int cc = wn * 32 + ni * 8 + 2 * tg;
                *reinterpret_cast<float2*>(&sP[r_lo * PST + cc]) =
                    make_float2(acc_s[mi][ni][0] * scale, acc_s[mi][ni][1] * scale);
                *reinterpret_cast<float2*>(&sP[r_hi * PST + cc]) =
                    make_float2(acc_s[mi][ni][2] * scale, acc_s[mi][ni][3] * scale);
            }
        }
        __syncthreads();

        // Online softmax: 2 threads per row, 32 cols each
        {
            int row  = tid >> 1;
            int half = tid & 1;
            float* pr = sP + row * PST + half * 32;
            float om = sM[row];
            float mx = -1e30f;
            #pragma unroll
            for (int j = 0; j < 32; j++) mx = fmaxf(mx, pr[j]);
            mx = fmaxf(mx, __shfl_xor_sync(0xffffffff, mx, 1));
            mx = fmaxf(mx, om);
            float sum = 0.f;
            #pragma unroll
            for (int j = 0; j < 32; j++) {
                float p = __expf(pr[j] - mx);
                pr[j] = p;
                sum += p;
            }
            sum += __shfl_xor_sync(0xffffffff, sum, 1);
            if (half == 0) {
                float sc = __expf(om - mx);
                sM[row] = mx;
                sL[row] = sL[row] * sc + sum;
                sS[row] = sc;
            }
        }
        __syncthreads();

        // Rescale O, then GEMM2: O[256 w][64 dd] += P V^T (k = m = 64)
        #pragma unroll
        for (int mi = 0; mi < 2; mi++) {
            int r_lo = wm * 32 + mi * 16 + g;
            float s0 = sS[r_lo], s1 = sS[r_lo + 8];
            #pragma unroll
            for (int ni = 0; ni < 4; ni++) {
                acc_o[mi][ni][0] *= s0; acc_o[mi][ni][1] *= s0;
                acc_o[mi][ni][2] *= s1; acc_o[mi][ni][3] *= s1;
            }
        }
        #pragma unroll
        for (int ks = 0; ks < 8; ks++) {
            const int k0 = ks * 8;
            uint32_t af[2][4], bf[4][2];
            #pragma unroll
            for (int mi = 0; mi < 2; mi++) {
                int m = wm * 32 + mi * 16 + g;
                af[mi][0] = __float_as_uint(sP[(m    ) * PST + k0 + tg    ]);
                af[mi][1] = __float_as_uint(sP[(m + 8) * PST + k0 + tg    ]);
                af[mi][2] = __float_as_uint(sP[(m    ) * PST + k0 + tg + 4]);
                af[mi][3] = __float_as_uint(sP[(m + 8) * PST + k0 + tg + 4]);
            }
            #pragma unroll
            for (int ni = 0; ni < 4; ni++) {
                int n = wn * 32 + ni * 8 + g;
                bf[ni][0] = __float_as_uint(V[n * VST + k0 + tg    ]);
                bf[ni][1] = __float_as_uint(V[n * VST + k0 + tg + 4]);
            }
            #pragma unroll
            for (int mi = 0; mi < 2; mi++)
                #pragma unroll
                for (int ni = 0; ni < 4; ni++)
                    mma_tf32(acc_o[mi][ni], af[mi], bf[ni]);
        }
        CP_WAIT0();
        __syncthreads();
    }

    // Final: O /= L, write g_newv[b, w0+w, h*64+dd]
    #pragma unroll
    for (int mi = 0; mi < 2; mi++) {
        int r_lo = wm * 32 + mi * 16 + g;
        int r_hi = r_lo + 8;
        float inv0 = 1.f / sL[r_lo];
        float inv1 = 1.f / sL[r_hi];
        float* out_lo = g_newv + ((size_t)(b * LL) + w0 + r_lo) * DD + h * HD;
        float* out_hi = g_newv + ((size_t)(b * LL) + w0 + r_hi) * DD + h * HD;
        #pragma unroll
        for (int ni = 0; ni < 4; ni++) {
            int cc = wn * 32 + ni * 8 + 2 * tg;
            *reinterpret_cast<float2*>(&out_lo[cc]) =
                make_float2(acc_o[mi][ni][0] * inv0, acc_o[mi][ni][1] * inv0);
            *reinterpret_cast<float2*>(&out_hi[cc]) =
                make_float2(acc_o[mi][ni][2] * inv1, acc_o[mi][ni][3] * inv1);
        }
    }
}

// ---------------------------------------------------------------------------
// Kernel 3 (mma.sync tf32 + cp.async): m = swish(new_v @ fc_w^T + fc_b)
// ---------------------------------------------------------------------------
#define FC_SMEM (4 * 128 * 36 * 4)

__device__ __forceinline__ void fc_issue(float* dsm, int buf, int c, int m0, int n0,
                                         const float* __restrict__ fw, int tid)
{
    const int k0g = c * 32;
    float* sA = dsm + buf * 4608;
    float* sB = dsm + 9216 + buf * 4608;
    #pragma unroll
    for (int r = 0; r < 4; r++) {
        int idx = tid + r * 256;
        int m = idx >> 3, kq = (idx & 7) * 4;
        cpa16(smem_u32(&sA[m * 36 + kq]), g_newv + (size_t)(m0 + m) * DD + k0g + kq);
    }
    #pragma unroll
    for (int r = 0; r < 4; r++) {
        int idx = tid + r * 256;
        int n = idx >> 3, kq = (idx & 7) * 4;
        cpa16(smem_u32(&sB[n * 36 + kq]), fw + (size_t)(n0 + n) * DD + k0g + kq);
    }
}

__global__ void __launch_bounds__(256, 2) fc_mma_kernel(const float* __restrict__ fw,
                                                        const float* __restrict__ fb)
{
    extern __shared__ float dsm[];

    const int m0  = blockIdx.x * 128;
    const int n0  = blockIdx.y * 128;
    const int tid = threadIdx.x;
    const int wid = tid >> 5;
    const int lane = tid & 31;
    const int g   = lane >> 2;
    const int tg  = lane & 3;
    const int wm  = wid & 1;
    const int wn  = wid >> 1;

    float acc[4][4][4];
    #pragma unroll
    for (int mi = 0; mi < 4; mi++)
        #pragma unroll
        for (int ni = 0; ni < 4; ni++)
            #pragma unroll
            for (int q = 0; q < 4; q++) acc[mi][ni][q] = 0.f;

    fc_issue(dsm, 0, 0, m0, n0, fw, tid);
    CPC();

    for (int c = 0; c < 16; c++) {
        const int cur = c & 1;
        if (c < 15) {
            fc_issue(dsm, cur ^ 1, c + 1, m0, n0, fw, tid);
            CPC();
            CP_WAIT1();
        } else {
            CP_WAIT0();
        }
        __syncthreads();

        const float* A  = dsm + cur * 4608;
        const float* Bm = dsm + 9216 + cur * 4608;

        #pragma unroll
        for (int ks = 0; ks < 4; ks++) {
            const int k0 = ks * 8;
            uint32_t af[4][4], bf[4][2];
            #pragma unroll
            for (int mi = 0; mi < 4; mi++) {
                int m = wm * 64 + mi * 16;
                af[mi][0] = __float_as_uint(A[(m + g    ) * 36 + k0 + tg    ]);
                af[mi][1] = __float_as_uint(A[(m + g + 8) * 36 + k0 + tg    ]);
                af[mi][2] = __float_as_uint(A[(m + g    ) * 36 + k0 + tg + 4]);
                af[mi][3] = __float_as_uint(A[(m + g + 8) * 36 + k0 + tg + 4]);
            }
            #pragma unroll
            for (int ni = 0; ni < 4; ni++) {
                int n = wn * 32 + ni * 8;
                bf[ni][0] = __float_as_uint(Bm[(n + g) * 36 + k0 + tg    ]);
                bf[ni][1] = __float_as_uint(Bm[(n + g) * 36 + k0 + tg + 4]);
            }
            #pragma unroll
            for (int mi = 0; mi < 4; mi++)
                #pragma unroll
                for (int ni = 0; ni < 4; ni++)
                    mma_tf32(acc[mi][ni], af[mi], bf[ni]);
        }
        __syncthreads();
    }

    #pragma unroll
    for (int mi = 0; mi < 4; mi++) {
        int m_lo = m0 + wm * 64 + mi * 16 + g;
        int m_hi = m_lo + 8;
        #pragma unroll
        for (int ni = 0; ni < 4; ni++) {
            int n = n0 + wn * 32 + ni * 8 + 2 * tg;
            float b0 = fb[n], b1 = fb[n + 1];
            float2 v0, v1;
            v0.x = swishf(acc[mi][ni][0] + b0);
            v0.y = swishf(acc[mi][ni][1] + b1);
            v1.x = swishf(acc[mi][ni][2] + b0);
            v1.y = swishf(acc[mi][ni][3] + b1);
            *reinterpret_cast<float2*>(&g_fc[(size_t)m_lo * DD + n]) = v0;
            *reinterpret_cast<float2*>(&g_fc[(size_t)m_hi * DD + n]) = v1;
        }
    }
}

// ---------------------------------------------------------------------------
// Kernel 4: out = layer_norm(2*x + g_fc). One warp per row of 512.
// ---------------------------------------------------------------------------
__global__ void ln_kernel(const float* __restrict__ x,
                          float* __restrict__ out)
{
    const int row  = blockIdx.x * 8 + (threadIdx.x >> 5);
    const int lane = threadIdx.x & 31;
    const float* mrow = g_fc + (size_t)row * DD;
    const float* xrow = x    + (size_t)row * DD;

    float tv[16];
    float sum = 0.f, sq = 0.f;
    #pragma unroll
    for (int t = 0; t < 16; t++) {
        int d = lane + 32 * t;
        float v = 2.f * xrow[d] + mrow[d];
        tv[t] = v;
        sum += v;
        sq  += v * v;
    }
    #pragma unroll
    for (int off = 16; off >= 1; off >>= 1) {
        sum += __shfl_xor_sync(0xffffffff, sum, off);
        sq  += __shfl_xor_sync(0xffffffff, sq,  off);
    }
    float mu  = sum * (1.f / 512.f);
    float var = sq * (1.f / 512.f) - mu * mu;
    float inv = rsqrtf(var + 1e-5f);

    float* orow = out + (size_t)row * DD;
    #pragma unroll
    for (int t = 0; t < 16; t++)
        orow[lane + 32 * t] = (tv[t] - mu) * inv;
}

// ---------------------------------------------------------------------------
extern "C" void kernel_launch(void* const* d_in, const int* in_sizes, int n_in,
                              void* d_out, int out_size)
{
    const float* x  = (const float*)d_in[0];
    const float* cw = (const float*)d_in[1];
    const float* cb = (const float*)d_in[2];
    const float* fw = (const float*)d_in[3];
    const float* fb = (const float*)d_in[4];
    float* out = (float*)d_out;

    cudaFuncSetAttribute(conv_mma_kernel,
                         cudaFuncAttributeMaxDynamicSharedMemorySize, CONV_SMEM);
    cudaFuncSetAttribute(attn_mma_kernel,
                         cudaFuncAttributeMaxDynamicSharedMemorySize, ATTN_SMEM);
    cudaFuncSetAttribute(fc_mma_kernel,
                         cudaFuncAttributeMaxDynamicSharedMemorySize, FC_SMEM);

    // 0) transpose + tf32-round weights
    wprep_kernel<<<(3 * OC * DD + 255) / 256, 256>>>(cw);

    // 1) conv+swish via mma.sync tf32 (pipelined)
    dim3 cgrid(LL / 128, OC / 128, BB);
    conv_mma_kernel<<<cgrid, 256, CONV_SMEM>>>(x, cb);

    // 2) attention via mma.sync tf32 (256-row tiles, 1 wave, pipelined K/V)
    dim3 agrid(LL / 256, HEADS, BB);
    attn_mma_kernel<<<agrid, 512, ATTN_SMEM>>>();

    // 3) fc + swish via mma.sync tf32 (pipelined)
    dim3 fgrid((BB * LL) / 128, DD / 128);
    fc_mma_kernel<<<fgrid, 256, FC_SMEM>>>(fw, fb);

    // 4) residual + layernorm
    ln_kernel<<<(BB * LL) / 8, 256>>>(x, out);
}

// round 8
// speedup vs baseline: 5.0055x; 1.0566x over previous
#include <cuda_runtime.h>
#include <cstdint>
#include <math.h>

#define HEADS 8
#define HD    64
#define BB    2
#define LL    2048
#define DD    512
#define OC    1536   // 3*HEADS*HD

// Scratch (device globals — no allocations allowed)
__device__ float g_qkv [BB * OC * LL];   // conv+swish output, [b, c, l]
__device__ float g_newv[BB * LL * DD];   // attention output, [b, l, h*HD+d]
__device__ float g_fc  [BB * LL * DD];   // fc+swish output,  [b, l, d]
__device__ float g_wt  [3 * OC * DD];    // transposed conv weights [t][o][i], tf32-rounded

__device__ __forceinline__ float swishf(float v) {
    return v / (1.f + __expf(-v));
}
__device__ __forceinline__ float to_tf32(float x) {
    float r; asm("cvt.rna.tf32.f32 %0, %1;" : "=f"(r) : "f"(x)); return r;
}
__device__ __forceinline__ uint32_t smem_u32(const void* p) {
    return (uint32_t)__cvta_generic_to_shared(p);
}
__device__ __forceinline__ void cpa16(uint32_t dst, const void* src) {
    asm volatile("cp.async.cg.shared.global [%0], [%1], 16;" :: "r"(dst), "l"(src));
}
__device__ __forceinline__ void cpa16p(uint32_t dst, const void* src, bool pred) {
    int sz = pred ? 16 : 0;
    asm volatile("cp.async.cg.shared.global [%0], [%1], 16, %2;" :: "r"(dst), "l"(src), "r"(sz));
}
#define CPC()      asm volatile("cp.async.commit_group;" ::: "memory")
#define CP_WAIT0() asm volatile("cp.async.wait_group 0;" ::: "memory")
#define CP_WAIT1() asm volatile("cp.async.wait_group 1;" ::: "memory")

// m16n8k8 tf32 mma: D(16x8,f32) += A(16x8,tf32,row) * B(8x8,tf32,col)
__device__ __forceinline__ void mma_tf32(float c[4], const uint32_t a[4], const uint32_t b[2]) {
    asm volatile(
        "mma.sync.aligned.m16n8k8.row.col.f32.tf32.tf32.f32 "
        "{%0,%1,%2,%3}, {%4,%5,%6,%7}, {%8,%9}, {%0,%1,%2,%3};"
        : "+f"(c[0]), "+f"(c[1]), "+f"(c[2]), "+f"(c[3])
        : "r"(a[0]), "r"(a[1]), "r"(a[2]), "r"(a[3]), "r"(b[0]), "r"(b[1]));
}
// ldmatrix: tf32 A-fragment (16x8) in one x4; B-fragment (8x8 from [n][k]) in one x2.
__device__ __forceinline__ void ldsm4(uint32_t r[4], uint32_t addr) {
    asm volatile("ldmatrix.sync.aligned.m8n8.x4.shared.b16 {%0,%1,%2,%3}, [%4];"
        : "=r"(r[0]), "=r"(r[1]), "=r"(r[2]), "=r"(r[3]) : "r"(addr));
}
__device__ __forceinline__ void ldsm2(uint32_t r[2], uint32_t addr) {
    asm volatile("ldmatrix.sync.aligned.m8n8.x2.shared.b16 {%0,%1}, [%2];"
        : "=r"(r[0]), "=r"(r[1]) : "r"(addr));
}

// ---------------------------------------------------------------------------
// Kernel 0: transpose conv weights to [t][o][i] with tf32 rounding.
// ---------------------------------------------------------------------------
__global__ void wprep_kernel(const float* __restrict__ w)
{
    int idx = blockIdx.x * 256 + threadIdx.x;
    if (idx < 3 * OC * DD) {
        int i   = idx & 511;
        int rem = idx >> 9;          // t*OC + o
        int o   = rem % OC;
        int t   = rem / OC;
        g_wt[idx] = to_tf32(w[(size_t)o * 1536 + i * 3 + t]);
    }
}

// ---------------------------------------------------------------------------
// Kernel 1 (mma.sync tf32 + cp.async + ldmatrix):
// Conv1d(D->OC,k=3,pad=1)+bias+swish -> g_qkv[b][o][l]
// ---------------------------------------------------------------------------
#define CONV_SMEM (4 * 128 * 36 * 4)

__device__ __forceinline__ void conv_issue(float* dsm, int buf, int c, int b,
                                           int o0, int l0,
                                           const float* __restrict__ x, int tid)
{
    const int t  = c >> 4;
    const int i0 = (c & 15) * 32;
    const float* wt = g_wt + ((size_t)t * OC + o0) * DD + i0;
    float* sA = dsm + buf * 4608;
    float* sB = dsm + 9216 + buf * 4608;
    #pragma unroll
    for (int r = 0; r < 4; r++) {
        int idx = tid + r * 256;
        int m = idx >> 3, kq = (idx & 7) * 4;
        cpa16(smem_u32(&sA[m * 36 + kq]), wt + (size_t)m * DD + kq);
    }
    #pragma unroll
    for (int r = 0; r < 4; r++) {
        int idx = tid + r * 256;
        int n = idx >> 3, kq = (idx & 7) * 4;
        int l = l0 + n + t - 1;
        bool ok = (l >= 0) && (l < LL);
        const float* src = ok ? (x + ((size_t)(b * LL + l)) * DD + i0 + kq) : x;
        cpa16p(smem_u32(&sB[n * 36 + kq]), src, ok);
    }
}

__global__ void __launch_bounds__(256, 2) conv_mma_kernel(const float* __restrict__ x,
                                                          const float* __restrict__ bias)
{
    extern __shared__ float dsm[];

    const int b   = blockIdx.z;
    const int l0  = blockIdx.x * 128;
    const int o0  = blockIdx.y * 128;
    const int tid = threadIdx.x;
    const int wid = tid >> 5;
    const int lane = tid & 31;
    const int g   = lane >> 2;
    const int tg  = lane & 3;
    const int wm  = wid & 1;
    const int wn  = wid >> 1;
    const int lr  = lane & 7;          // ldsm row within 8-row segment
    const int ls1 = (lane >> 3) & 1;   // ldsm: row-half select (x4) / col-half (x2)
    const int ls2 = lane >> 4;         // ldsm x4: col-half select

    float acc[4][4][4];
    #pragma unroll
    for (int mi = 0; mi < 4; mi++)
        #pragma unroll
        for (int ni = 0; ni < 4; ni++)
            #pragma unroll
            for (int q = 0; q < 4; q++) acc[mi][ni][q] = 0.f;

    conv_issue(dsm, 0, 0, b, o0, l0, x, tid);
    CPC();

    for (int c = 0; c < 48; c++) {
        const int cur = c & 1;
        if (c < 47) {
            conv_issue(dsm, cur ^ 1, c + 1, b, o0, l0, x, tid);
            CPC();
            CP_WAIT1();
        } else {
            CP_WAIT0();
        }
        __syncthreads();

        const float* A  = dsm + cur * 4608;
        const float* Bm = dsm + 9216 + cur * 4608;

        #pragma unroll
        for (int ks = 0; ks < 4; ks++) {
            const int k0 = ks * 8;
            uint32_t af[4][4], bf[4][2];
            #pragma unroll
            for (int mi = 0; mi < 4; mi++) {
                int row = wm * 64 + mi * 16 + ls1 * 8 + lr;
                ldsm4(af[mi], smem_u32(&A[row * 36 + k0 + ls2 * 4]));
            }
            #pragma unroll
            for (int ni = 0; ni < 4; ni++) {
                int row = wn * 32 + ni * 8 + lr;
                ldsm2(bf[ni], smem_u32(&Bm[row * 36 + k0 + ls1 * 4]));
            }
            #pragma unroll
            for (int mi = 0; mi < 4; mi++)
                #pragma unroll
                for (int ni = 0; ni < 4; ni++)
                    mma_tf32(acc[mi][ni], af[mi], bf[ni]);
        }
        __syncthreads();
    }

    #pragma unroll
    for (int mi = 0; mi < 4; mi++) {
        int o_lo = o0 + wm * 64 + mi * 16 + g;
        int o_hi = o_lo + 8;
        float b_lo = bias[o_lo], b_hi = bias[o_hi];
        float* row_lo = g_qkv + ((size_t)b * OC + o_lo) * LL;
        float* row_hi = g_qkv + ((size_t)b * OC + o_hi) * LL;
        #pragma unroll
        for (int ni = 0; ni < 4; ni++) {
            int l = l0 + wn * 32 + ni * 8 + 2 * tg;
            float2 v0, v1;
            v0.x = swishf(acc[mi][ni][0] + b_lo);
            v0.y = swishf(acc[mi][ni][1] + b_lo);
            v1.x = swishf(acc[mi][ni][2] + b_hi);
            v1.y = swishf(acc[mi][ni][3] + b_hi);
            *reinterpret_cast<float2*>(&row_lo[l]) = v0;
            *reinterpret_cast<float2*>(&row_hi[l]) = v1;
        }
    }
}

// ---------------------------------------------------------------------------
// Kernel 2 (mma.sync tf32 + cp.async + ldmatrix): flash attention.
// CTA = (b, h, 256-row w tile), 512 threads (wm 0..7 x wn 0..1).
// Q stored [w][d] (row-major, scalar transposed fill, one-time) -> A via ldsm4.
// K [d][m] via cp.async (B-frag scalar, conflict-free). V [dd][m] -> B via ldsm2.
// P [w][m] -> A via ldsm4. Strides 68 (=4 mod 32) for ldsm; KST=72 (=8 mod 32).
// ---------------------------------------------------------------------------
#define QST 68
#define KST 72
#define VST 68
#define PST 68
#define ATTN_SMEM ((256*QST + 2*64*KST + 2*64*VST + 256*PST + 3*256) * 4)

__device__ __forceinline__ void attn_issue_kv(float* sK, float* sV, int buf,
                                              const float* __restrict__ kbase,
                                              const float* __restrict__ vbase,
                                              int m0, int tid)
{
    float* k = sK + buf * 64 * KST;
    float* v = sV + buf * 64 * VST;
    #pragma unroll
    for (int r = 0; r < 2; r++) {
        int idx = tid + r * 512;
        int dd = idx >> 4;
        int ms = (idx & 15) * 4;
        cpa16(smem_u32(&k[dd * KST + ms]), kbase + (size_t)dd * LL + m0 + ms);
    }
    #pragma unroll
    for (int r = 0; r < 2; r++) {
        int idx = tid + r * 512;
        int dd = idx >> 4;
        int ms = (idx & 15) * 4;
        cpa16(smem_u32(&v[dd * VST + ms]), vbase + (size_t)dd * LL + m0 + ms);
    }
}

__global__ void __launch_bounds__(512, 1) attn_mma_kernel()
{
    extern __shared__ float dsm[];
    float* sQ = dsm;                       // [256][QST]  (w, d)
    float* sK = sQ + 256 * QST;            // [2][64][KST] (d, m)
    float* sV = sK + 2 * 64 * KST;         // [2][64][VST] (dd, m)
    float* sP = sV + 2 * 64 * VST;         // [256][PST]  (w, m)
    float* sM = sP + 256 * PST;            // [256]
    float* sL = sM + 256;                  // [256]
    float* sS = sL + 256;                  // [256]

    const int b   = blockIdx.z;
    const int h   = blockIdx.y;
    const int w0  = blockIdx.x * 256;
    const int tid = threadIdx.x;
    const int wid = tid >> 5;
    const int lane = tid & 31;
    const int g   = lane >> 2;
    const int tg  = lane & 3;
    const int wm  = wid & 7;        // 0..7 -> 32 w-rows each
    const int wn  = wid >> 3;       // 0..1 -> 32 cols each
    const int lr  = lane & 7;
    const int ls1 = (lane >> 3) & 1;
    const int ls2 = lane >> 4;

    const float scale = rsqrtf((float)LL);
    const float* qbase = g_qkv + ((size_t)b * OC + h * 192) * LL;
    const float* kbase = qbase + (size_t)64 * LL;
    const float* vbase = qbase + (size_t)128 * LL;

    attn_issue_kv(sK, sV, 0, kbase, vbase, 0, tid);
    CPC();

    // Q tile: [256 w][64 d], transposed scalar fill (coalesced gmem reads)
    #pragma unroll
    for (int r = 0; r < 32; r++) {
        int idx = tid + r * 512;
        int ww = idx & 255;
        int dd = idx >> 8;
        sQ[ww * QST + dd] = qbase[(size_t)dd * LL + w0 + ww];
    }
    if (tid < 256) { sM[tid] = -1e30f; sL[tid] = 0.f; }

    float acc_o[2][4][4];
    #pragma unroll
    for (int mi = 0; mi < 2; mi++)
        #pragma unroll
        for (int ni = 0; ni < 4; ni++)
            #pragma unroll
            for (int q = 0; q < 4; q++) acc_o[mi][ni][q] = 0.f;

    CP_WAIT0();
    __syncthreads();

    for (int c = 0; c < 32; c++) {
        const int cur = c & 1;
        if (c < 31) {
            attn_issue_kv(sK, sV, cur ^ 1, kbase, vbase, (c + 1) * 64, tid);
            CPC();
        }
        const float* K = sK + cur * 64 * KST;
        const float* V = sV + cur * 64 * VST;

        // GEMM1: S[256 w][64 m] = Q K^T (k = d = 64)
        float acc_s[2][4][4];
        #pragma unroll
        for (int mi = 0; mi < 2; mi++)
            #pragma unroll
            for (int ni = 0; ni < 4; ni++)
                #pragma unroll
                for (int q = 0; q < 4; q++) acc_s[mi][ni][q] = 0.f;

        #pragma unroll
        for (int ks = 0; ks < 8; ks++) {
            const int k0 = ks * 8;
            uint32_t af[2][4], bf[4][2];
            #pragma unroll
            for (int mi = 0; mi < 2; mi++) {
                int row = wm * 32 + mi * 16 + ls1 * 8 + lr;
                ldsm4(af[mi], smem_u32(&sQ[row * QST + k0 + ls2 * 4]));
            }
            #pragma unroll
            for (int ni = 0; ni < 4; ni++) {
                int n = wn * 32 + ni * 8 + g;
                bf[ni][0] = __float_as_uint(K[(k0 + tg    ) * KST + n]);
                bf[ni][1] = __float_as_uint(K[(k0 + tg + 4) * KST + n]);
            }
            #pragma unroll
            for (int mi = 0; mi < 2; mi++)
                #pragma unroll
                for (int ni = 0; ni < 4; ni++)
                    mma_tf32(acc_s[mi][ni], af[mi], bf[ni]);
        }

        // Write S * scale to sP
        #pragma unroll
        for (int mi = 0; mi < 2; mi++) {
            int r_lo = wm * 32 + mi * 16 + g;
            int r_hi = r_lo + 8;
            #pragma unroll
            for (int ni = 0; ni < 4; ni++) {
                int cc = wn * 32 + ni * 8 + 2 * tg;
                *reinterpret_cast<float2*>(&sP[r_lo * PST + cc]) =
                    make_float2(acc_s[mi][ni][0] * scale, acc_s[mi][ni][1] * scale);
                *reinterpret_cast<float2*>(&sP[r_hi * PST + cc]) =
                    make_float2(acc_s[mi][ni][2] * scale, acc_s[mi][ni][3] * scale);
            }
        }
        __syncthreads();

        // Online softmax: 2 threads per row, 32 cols each
        {
            int row  = tid >> 1;
            int half = tid & 1;
            float* pr = sP + row * PST + half * 32;
            float om = sM[row];
            float mx = -1e30f;
            #pragma unroll
            for (int j = 0; j < 32; j++) mx = fmaxf(mx, pr[j]);
            mx = fmaxf(mx, __shfl_xor_sync(0xffffffff, mx, 1));
            mx = fmaxf(mx, om);
            float sum = 0.f;
            #pragma unroll
            for (int j = 0; j < 32; j++) {
                float p = __expf(pr[j] - mx);
                pr[j] = p;
                sum += p;
            }
            sum += __shfl_xor_sync(0xffffffff, sum, 1);
            if (half == 0) {
                float sc = __expf(om - mx);
                sM[row] = mx;
                sL[row] = sL[row] * sc + sum;
                sS[row] = sc;
            }
        }
        __syncthreads();

        // Rescale O, then GEMM2: O[256 w][64 dd] += P V^T (k = m = 64)
        #pragma unroll
        for (int mi = 0; mi < 2; mi++) {
            int r_lo = wm * 32 + mi * 16 + g;
            float s0 = sS[r_lo], s1 = sS[r_lo + 8];
            #pragma unroll
            for (int ni = 0; ni < 4; ni++) {
                acc_o[mi][ni][0] *= s0; acc_o[mi][ni][1] *= s0;
                acc_o[mi][ni][2] *= s1; acc_o[mi][ni][3] *= s1;
            }
        }
        #pragma unroll
        for (int ks = 0; ks < 8; ks++) {
            const int k0 = ks * 8;
            uint32_t af[2][4], bf[4][2];
            #pragma unroll
            for (int mi = 0; mi < 2; mi++) {
                int row = wm * 32 + mi * 16 + ls1 * 8 + lr;
                ldsm4(af[mi], smem_u32(&sP[row * PST + k0 + ls2 * 4]));
            }
            #pragma unroll
            for (int ni = 0; ni < 4; ni++) {
                int row = wn * 32 + ni * 8 + lr;
                ldsm2(bf[ni], smem_u32(&V[row * VST + k0 + ls1 * 4]));
            }
            #pragma unroll
            for (int mi = 0; mi < 2; mi++)
                #pragma unroll
                for (int ni = 0; ni < 4; ni++)
                    mma_tf32(acc_o[mi][ni], af[mi], bf[ni]);
        }
        CP_WAIT0();
        __syncthreads();
    }

    // Final: O /= L, write g_newv[b, w0+w, h*64+dd]
    #pragma unroll
    for (int mi = 0; mi < 2; mi++) {
        int r_lo = wm * 32 + mi * 16 + g;
        int r_hi = r_lo + 8;
        float inv0 = 1.f / sL[r_lo];
        float inv1 = 1.f / sL[r_hi];
        float* out_lo = g_newv + ((size_t)(b * LL) + w0 + r_lo) * DD + h * HD;
        float* out_hi = g_newv + ((size_t)(b * LL) + w0 + r_hi) * DD + h * HD;
        #pragma unroll
        for (int ni = 0; ni < 4; ni++) {
            int cc = wn * 32 + ni * 8 + 2 * tg;
            *reinterpret_cast<float2*>(&out_lo[cc]) =
                make_float2(acc_o[mi][ni][0] * inv0, acc_o[mi][ni][1] * inv0);
            *reinterpret_cast<float2*>(&out_hi[cc]) =
                make_float2(acc_o[mi][ni][2] * inv1, acc_o[mi][ni][3] * inv1);
        }
    }
}

// ---------------------------------------------------------------------------
// Kernel 3 (mma.sync tf32 + cp.async + ldmatrix): m = swish(new_v@fc_w^T+fc_b)
// ---------------------------------------------------------------------------
#define FC_SMEM (4 * 128 * 36 * 4)

__device__ __forceinline__ void fc_issue(float* dsm, int buf, int c, int m0, int n0,
                                         const float* __restrict__ fw, int tid)
{
    const int k0g = c * 32;
    float* sA = dsm + buf * 4608;
    float* sB = dsm + 9216 + buf * 4608;
    #pragma unroll
    for (int r = 0; r < 4; r++) {
        int idx = tid + r * 256;
        int m = idx >> 3, kq = (idx & 7) * 4;
        cpa16(smem_u32(&sA[m * 36 + kq]), g_newv + (size_t)(m0 + m) * DD + k0g + kq);
    }
    #pragma unroll
    for (int r = 0; r < 4; r++) {
        int idx = tid + r * 256;
        int n = idx >> 3, kq = (idx & 7) * 4;
        cpa16(smem_u32(&sB[n * 36 + kq]), fw + (size_t)(n0 + n) * DD + k0g + kq);
    }
}

__global__ void __launch_bounds__(256, 2) fc_mma_kernel(const float* __restrict__ fw,
                                                        const float* __restrict__ fb)
{
    extern __shared__ float dsm[];

    const int m0  = blockIdx.x * 128;
    const int n0  = blockIdx.y * 128;
    const int tid = threadIdx.x;
    const int wid = tid >> 5;
    const int lane = tid & 31;
    const int g   = lane >> 2;
    const int tg  = lane & 3;
    const int wm  = wid & 1;
    const int wn  = wid >> 1;
    const int lr  = lane & 7;
    const int ls1 = (lane >> 3) & 1;
    const int ls2 = lane >> 4;

    float acc[4][4][4];
    #pragma unroll
    for (int mi = 0; mi < 4; mi++)
        #pragma unroll
        for (int ni = 0; ni < 4; ni++)
            #pragma unroll
            for (int q = 0; q < 4; q++) acc[mi][ni][q] = 0.f;

    fc_issue(dsm, 0, 0, m0, n0, fw, tid);
    CPC();

    for (int c = 0; c < 16; c++) {
        const int cur = c & 1;
        if (c < 15) {
            fc_issue(dsm, cur ^ 1, c + 1, m0, n0, fw, tid);
            CPC();
            CP_WAIT1();
        } else {
            CP_WAIT0();
        }
        __syncthreads();

        const float* A  = dsm + cur * 4608;
        const float* Bm = dsm + 9216 + cur * 4608;

        #pragma unroll
        for (int ks = 0; ks < 4; ks++) {
            const int k0 = ks * 8;
            uint32_t af[4][4], bf[4][2];
            #pragma unroll
            for (int mi = 0; mi < 4; mi++) {
                int row = wm * 64 + mi * 16 + ls1 * 8 + lr;
                ldsm4(af[mi], smem_u32(&A[row * 36 + k0 + ls2 * 4]));
            }
            #pragma unroll
            for (int ni = 0; ni < 4; ni++) {
                int row = wn * 32 + ni * 8 + lr;
                ldsm2(bf[ni], smem_u32(&Bm[row * 36 + k0 + ls1 * 4]));
            }
            #pragma unroll
            for (int mi = 0; mi < 4; mi++)
                #pragma unroll
                for (int ni = 0; ni < 4; ni++)
                    mma_tf32(acc[mi][ni], af[mi], bf[ni]);
        }
        __syncthreads();
    }

    #pragma unroll
    for (int mi = 0; mi < 4; mi++) {
        int m_lo = m0 + wm * 64 + mi * 16 + g;
        int m_hi = m_lo + 8;
        #pragma unroll
        for (int ni = 0; ni < 4; ni++) {
            int n = n0 + wn * 32 + ni * 8 + 2 * tg;
            float b0 = fb[n], b1 = fb[n + 1];
            float2 v0, v1;
            v0.x = swishf(acc[mi][ni][0] + b0);
            v0.y = swishf(acc[mi][ni][1] + b1);
            v1.x = swishf(acc[mi][ni][2] + b0);
            v1.y = swishf(acc[mi][ni][3] + b1);
            *reinterpret_cast<float2*>(&g_fc[(size_t)m_lo * DD + n]) = v0;
            *reinterpret_cast<float2*>(&g_fc[(size_t)m_hi * DD + n]) = v1;
        }
    }
}

// ---------------------------------------------------------------------------
// Kernel 4: out = layer_norm(2*x + g_fc). One warp per row of 512.
// ---------------------------------------------------------------------------
__global__ void ln_kernel(const float* __restrict__ x,
                          float* __restrict__ out)
{
    const int row  = blockIdx.x * 8 + (threadIdx.x >> 5);
    const int lane = threadIdx.x & 31;
    const float* mrow = g_fc + (size_t)row * DD;
    const float* xrow = x    + (size_t)row * DD;

    float tv[16];
    float sum = 0.f, sq = 0.f;
    #pragma unroll
    for (int t = 0; t < 16; t++) {
        int d = lane + 32 * t;
        float v = 2.f * xrow[d] + mrow[d];
        tv[t] = v;
        sum += v;
        sq  += v * v;
    }
    #pragma unroll
    for (int off = 16; off >= 1; off >>= 1) {
        sum += __shfl_xor_sync(0xffffffff, sum, off);
        sq  += __shfl_xor_sync(0xffffffff, sq,  off);
    }
    float mu  = sum * (1.f / 512.f);
    float var = sq * (1.f / 512.f) - mu * mu;
    float inv = rsqrtf(var + 1e-5f);

    float* orow = out + (size_t)row * DD;
    #pragma unroll
    for (int t = 0; t < 16; t++)
        orow[lane + 32 * t] = (tv[t] - mu) * inv;
}

// ---------------------------------------------------------------------------
extern "C" void kernel_launch(void* const* d_in, const int* in_sizes, int n_in,
                              void* d_out, int out_size)
{
    const float* x  = (const float*)d_in[0];
    const float* cw = (const float*)d_in[1];
    const float* cb = (const float*)d_in[2];
    const float* fw = (const float*)d_in[3];
    const float* fb = (const float*)d_in[4];
    float* out = (float*)d_out;

    cudaFuncSetAttribute(conv_mma_kernel,
                         cudaFuncAttributeMaxDynamicSharedMemorySize, CONV_SMEM);
    cudaFuncSetAttribute(attn_mma_kernel,
                         cudaFuncAttributeMaxDynamicSharedMemorySize, ATTN_SMEM);
    cudaFuncSetAttribute(fc_mma_kernel,
                         cudaFuncAttributeMaxDynamicSharedMemorySize, FC_SMEM);

    // 0) transpose + tf32-round weights
    wprep_kernel<<<(3 * OC * DD + 255) / 256, 256>>>(cw);

    // 1) conv+swish via mma.sync tf32 (pipelined + ldmatrix)
    dim3 cgrid(LL / 128, OC / 128, BB);
    conv_mma_kernel<<<cgrid, 256, CONV_SMEM>>>(x, cb);

    // 2) attention via mma.sync tf32 (1 wave, pipelined K/V, ldmatrix)
    dim3 agrid(LL / 256, HEADS, BB);
    attn_mma_kernel<<<agrid, 512, ATTN_SMEM>>>();

    // 3) fc + swish via mma.sync tf32 (pipelined + ldmatrix)
    dim3 fgrid((BB * LL) / 128, DD / 128);
    fc_mma_kernel<<<fgrid, 256, FC_SMEM>>>(fw, fb);

    // 4) residual + layernorm
    ln_kernel<<<(BB * LL) / 8, 256>>>(x, out);
}